// round 1
// baseline (speedup 1.0000x reference)
#include <cuda_runtime.h>

#define Tt 4
#define Nn 50000
#define Ee 800000
#define Dd 256
#define D4 64   // Dd/4

// Scratch (static device globals -- no allocation in kernel_launch)
__device__ float g_a[(size_t)Nn * Dd];
__device__ float g_h[(size_t)Nn * Dd];
__device__ float g_b[(size_t)Nn * Dd];
__device__ float g_dinv[Nn];
__device__ float g_norm[Ee];

__device__ __forceinline__ void red_add_v4(float4* p, float4 v) {
    asm volatile("red.global.add.v4.f32 [%0], {%1, %2, %3, %4};"
                 :: "l"(p), "f"(v.x), "f"(v.y), "f"(v.z), "f"(v.w)
                 : "memory");
}

__global__ void k_deg_init(float* __restrict__ deg) {
    int i = blockIdx.x * blockDim.x + threadIdx.x;
    if (i < Nn) deg[i] = 1.0f;   // self-loop weight
}

__global__ void k_deg_scatter(const int* __restrict__ col, const float* __restrict__ w,
                              float* __restrict__ deg) {
    int e = blockIdx.x * blockDim.x + threadIdx.x;
    if (e < Ee) atomicAdd(&deg[col[e]], w[e]);
}

__global__ void k_finalize_dinv(float* __restrict__ deg) {
    int i = blockIdx.x * blockDim.x + threadIdx.x;
    if (i < Nn) {
        float d = deg[i];
        deg[i] = (d > 0.0f) ? rsqrtf(d) : 0.0f;
    }
}

__global__ void k_norm(const int* __restrict__ row, const int* __restrict__ col,
                       const float* __restrict__ w, const float* __restrict__ dinv,
                       float* __restrict__ norm) {
    int e = blockIdx.x * blockDim.x + threadIdx.x;
    if (e < Ee) norm[e] = dinv[row[e]] * w[e] * dinv[col[e]];
}

__global__ void k_gather(const int* __restrict__ ids, const float4* __restrict__ emb,
                         float4* __restrict__ x) {
    int idx = blockIdx.x * blockDim.x + threadIdx.x;
    if (idx < Nn * D4) {
        int i = idx >> 6, q = idx & 63;
        x[idx] = emb[(size_t)ids[i] * D4 + q];
    }
}

// H = X @ W  (fp32, 128x128x16 block tile, 8x8 per thread)
// Fused epilogue: OUT = dinv[i]^2 * H[i] + bias  (self-loop + bias init)
__global__ void __launch_bounds__(256)
k_gemm(const float* __restrict__ X, const float* __restrict__ W,
       const float* __restrict__ bias, const float* __restrict__ dinv,
       float* __restrict__ H, float* __restrict__ OUT) {
    const int BM = 128, BN = 128, BK = 16, TM = 8, TN = 8;
    __shared__ float As[BK][BM + 4];
    __shared__ float Bs[BK][BN];

    const int tid  = threadIdx.x;
    const int m0   = blockIdx.x * BM;
    const int n0   = blockIdx.y * BN;
    const int arow = tid >> 2;          // 0..63
    const int acol = (tid & 3) << 2;    // 0,4,8,12
    const int brow = tid >> 5;          // 0..7
    const int bcol = (tid & 31) << 2;   // 0..124
    const int tr   = (tid >> 4) * TM;
    const int tc   = (tid & 15) * TN;

    float acc[TM][TN] = {};

    for (int k0 = 0; k0 < Dd; k0 += BK) {
#pragma unroll
        for (int i = 0; i < 2; i++) {
            int r  = arow + i * 64;
            int gm = m0 + r;
            float4 v = make_float4(0.f, 0.f, 0.f, 0.f);
            if (gm < Nn) v = *(const float4*)(X + (size_t)gm * Dd + k0 + acol);
            As[acol + 0][r] = v.x;
            As[acol + 1][r] = v.y;
            As[acol + 2][r] = v.z;
            As[acol + 3][r] = v.w;
        }
#pragma unroll
        for (int i = 0; i < 2; i++) {
            int r = brow + i * 8;
            *(float4*)&Bs[r][bcol] = *(const float4*)(W + (size_t)(k0 + r) * Dd + n0 + bcol);
        }
        __syncthreads();

#pragma unroll
        for (int kk = 0; kk < BK; kk++) {
            float ar[TM], br[TN];
#pragma unroll
            for (int i = 0; i < TM; i++) ar[i] = As[kk][tr + i];
#pragma unroll
            for (int j = 0; j < TN; j++) br[j] = Bs[kk][tc + j];
#pragma unroll
            for (int i = 0; i < TM; i++)
#pragma unroll
                for (int j = 0; j < TN; j++)
                    acc[i][j] = fmaf(ar[i], br[j], acc[i][j]);
        }
        __syncthreads();
    }

#pragma unroll
    for (int i = 0; i < TM; i++) {
        int gm = m0 + tr + i;
        if (gm >= Nn) continue;
        float s = dinv[gm];
        s = s * s;
#pragma unroll
        for (int j = 0; j < TN; j += 4) {
            int gc = n0 + tc + j;
            float4 hv = make_float4(acc[i][j], acc[i][j + 1], acc[i][j + 2], acc[i][j + 3]);
            *(float4*)(H + (size_t)gm * Dd + gc) = hv;
            float4 bv = *(const float4*)(bias + gc);
            float4 ov = make_float4(fmaf(s, hv.x, bv.x), fmaf(s, hv.y, bv.y),
                                    fmaf(s, hv.z, bv.z), fmaf(s, hv.w, bv.w));
            *(float4*)(OUT + (size_t)gm * Dd + gc) = ov;
        }
    }
}

// OUT[col[e]] += norm[e] * H[row[e]]  via vector reductions.
// 16 threads per edge, each handles 4 float4 chunks (q, q+16, q+32, q+48).
__global__ void k_scatter(const int* __restrict__ row, const int* __restrict__ col,
                          const float* __restrict__ norm, const float4* __restrict__ h,
                          float4* __restrict__ out) {
    int idx = blockIdx.x * blockDim.x + threadIdx.x;
    if (idx >= Ee * 16) return;
    int e = idx >> 4, q = idx & 15;
    float nm = norm[e];
    int r = row[e], c = col[e];
    const float4* hp = h + (size_t)r * D4 + q;
    float4* op = out + (size_t)c * D4 + q;
#pragma unroll
    for (int j = 0; j < 4; j++) {
        float4 v = hp[j * 16];
        v.x *= nm; v.y *= nm; v.z *= nm; v.w *= nm;
        red_add_v4(op + j * 16, v);
    }
}

extern "C" void kernel_launch(void* const* d_in, const int* in_sizes, int n_in,
                              void* d_out, int out_size) {
    const int*   ids_all = (const int*)d_in[0];    // (T, N)
    const int*   ei_all  = (const int*)d_in[1];    // (T, 2, E)
    const float* w_all   = (const float*)d_in[2];  // (T, E)
    const float* emb     = (const float*)d_in[3];  // (VOCAB, D)
    const float* Ws[3] = {(const float*)d_in[4], (const float*)d_in[6], (const float*)d_in[8]};
    const float* bs[3] = {(const float*)d_in[5], (const float*)d_in[7], (const float*)d_in[9]};
    float* out = (float*)d_out;

    void *pa, *ph, *pb, *pd, *pn;
    cudaGetSymbolAddress(&pa, g_a);
    cudaGetSymbolAddress(&ph, g_h);
    cudaGetSymbolAddress(&pb, g_b);
    cudaGetSymbolAddress(&pd, g_dinv);
    cudaGetSymbolAddress(&pn, g_norm);
    float* A    = (float*)pa;
    float* Hh   = (float*)ph;
    float* B    = (float*)pb;
    float* dinv = (float*)pd;
    float* nrm  = (float*)pn;

    const int TPB = 256;
    dim3 ggrid((Nn + 127) / 128, Dd / 128);

    for (int t = 0; t < Tt; t++) {
        const int*   row  = ei_all + (size_t)t * 2 * Ee;
        const int*   col  = row + Ee;
        const float* w    = w_all + (size_t)t * Ee;
        const int*   ids  = ids_all + (size_t)t * Nn;
        float*       outT = out + (size_t)t * Nn * Dd;

        k_deg_init<<<(Nn + TPB - 1) / TPB, TPB>>>(dinv);
        k_deg_scatter<<<(Ee + TPB - 1) / TPB, TPB>>>(col, w, dinv);
        k_finalize_dinv<<<(Nn + TPB - 1) / TPB, TPB>>>(dinv);
        k_norm<<<(Ee + TPB - 1) / TPB, TPB>>>(row, col, w, dinv, nrm);
        k_gather<<<(Nn * D4 + TPB - 1) / TPB, TPB>>>(ids, (const float4*)emb, (float4*)A);

        struct { const float* X; float* OUT; } io[3] = {{A, B}, {B, A}, {A, outT}};
        for (int l = 0; l < 3; l++) {
            k_gemm<<<ggrid, 256>>>(io[l].X, Ws[l], bs[l], dinv, Hh, io[l].OUT);
            k_scatter<<<(Ee * 16 + TPB - 1) / TPB, TPB>>>(row, col, nrm,
                                                          (const float4*)Hh,
                                                          (float4*)io[l].OUT);
        }
    }
}

// round 2
// speedup vs baseline: 1.2421x; 1.2421x over previous
#include <cuda_runtime.h>

#define Tt 4
#define Nn 50000
#define Ee 800000
#define Dd 256
#define D4 64   // Dd/4

// Scratch (static device globals -- no allocation in kernel_launch)
__device__ float g_a[(size_t)Nn * Dd];
__device__ float g_h[(size_t)Nn * Dd];
__device__ float g_b[(size_t)Nn * Dd];
__device__ float g_dinv[Nn];
__device__ int   g_cnt[Nn];
__device__ int   g_cur[Nn];
__device__ int   g_ptr[Nn + 1];
__device__ int   g_erow[Ee];
__device__ float g_enorm[Ee];

// deg = 1 (self loop), cnt = 0
__global__ void k_init(float* __restrict__ deg, int* __restrict__ cnt) {
    int i = blockIdx.x * blockDim.x + threadIdx.x;
    if (i < Nn) { deg[i] = 1.0f; cnt[i] = 0; }
}

// histogram + weighted in-degree, both keyed by col
__global__ void k_edge_prep(const int* __restrict__ col, const float* __restrict__ w,
                            float* __restrict__ deg, int* __restrict__ cnt) {
    int e = blockIdx.x * blockDim.x + threadIdx.x;
    if (e < Ee) {
        int c = col[e];
        atomicAdd(&deg[c], w[e]);
        atomicAdd(&cnt[c], 1);
    }
}

__global__ void k_finalize_dinv(float* __restrict__ deg) {
    int i = blockIdx.x * blockDim.x + threadIdx.x;
    if (i < Nn) {
        float d = deg[i];
        deg[i] = (d > 0.0f) ? rsqrtf(d) : 0.0f;
    }
}

// Single-block exclusive scan of cnt -> ptr (Nn+1 entries), cursor copy.
__global__ void __launch_bounds__(1024)
k_scan(const int* __restrict__ cnt, int* __restrict__ ptr, int* __restrict__ cur) {
    __shared__ int warp_tot[32];
    __shared__ int carry_sh;
    int tid = threadIdx.x;
    int lane = tid & 31, wid = tid >> 5;
    if (tid == 0) { carry_sh = 0; ptr[0] = 0; }
    __syncthreads();

    for (int base = 0; base < Nn; base += 1024) {
        int i = base + tid;
        int v = (i < Nn) ? cnt[i] : 0;
        // warp inclusive scan
        int s = v;
#pragma unroll
        for (int off = 1; off < 32; off <<= 1) {
            int t = __shfl_up_sync(0xffffffffu, s, off);
            if (lane >= off) s += t;
        }
        if (lane == 31) warp_tot[wid] = s;
        __syncthreads();
        if (wid == 0) {
            int ws = warp_tot[lane];
#pragma unroll
            for (int off = 1; off < 32; off <<= 1) {
                int t = __shfl_up_sync(0xffffffffu, ws, off);
                if (lane >= off) ws += t;
            }
            warp_tot[lane] = ws;
        }
        __syncthreads();
        int incl = s + (wid > 0 ? warp_tot[wid - 1] : 0) + carry_sh;
        if (i < Nn) ptr[i + 1] = incl;
        __syncthreads();
        if (tid == 1023) carry_sh = incl;
        __syncthreads();
    }
    for (int i = tid; i < Nn; i += 1024) cur[i] = ptr[i];
}

// Permute edges into destination buckets; fuse norm computation.
__global__ void k_permute(const int* __restrict__ row, const int* __restrict__ col,
                          const float* __restrict__ w, const float* __restrict__ dinv,
                          int* __restrict__ cur, int* __restrict__ erow,
                          float* __restrict__ enorm) {
    int e = blockIdx.x * blockDim.x + threadIdx.x;
    if (e < Ee) {
        int r = row[e], c = col[e];
        float nm = dinv[r] * w[e] * dinv[c];
        int pos = atomicAdd(&cur[c], 1);
        erow[pos] = r;
        enorm[pos] = nm;
    }
}

__global__ void k_gather(const int* __restrict__ ids, const float4* __restrict__ emb,
                         float4* __restrict__ x) {
    int idx = blockIdx.x * blockDim.x + threadIdx.x;
    if (idx < Nn * D4) {
        int i = idx >> 6, q = idx & 63;
        x[idx] = emb[(size_t)ids[i] * D4 + q];
    }
}

// H = X @ W  (fp32, 128x128x16 block tile, 8x8 per thread)
__global__ void __launch_bounds__(256)
k_gemm(const float* __restrict__ X, const float* __restrict__ W,
       float* __restrict__ H) {
    const int BM = 128, BN = 128, BK = 16, TM = 8, TN = 8;
    __shared__ float As[BK][BM + 4];
    __shared__ float Bs[BK][BN];

    const int tid  = threadIdx.x;
    const int m0   = blockIdx.x * BM;
    const int n0   = blockIdx.y * BN;
    const int arow = tid >> 2;
    const int acol = (tid & 3) << 2;
    const int brow = tid >> 5;
    const int bcol = (tid & 31) << 2;
    const int tr   = (tid >> 4) * TM;
    const int tc   = (tid & 15) * TN;

    float acc[TM][TN] = {};

    for (int k0 = 0; k0 < Dd; k0 += BK) {
#pragma unroll
        for (int i = 0; i < 2; i++) {
            int r  = arow + i * 64;
            int gm = m0 + r;
            float4 v = make_float4(0.f, 0.f, 0.f, 0.f);
            if (gm < Nn) v = *(const float4*)(X + (size_t)gm * Dd + k0 + acol);
            As[acol + 0][r] = v.x;
            As[acol + 1][r] = v.y;
            As[acol + 2][r] = v.z;
            As[acol + 3][r] = v.w;
        }
#pragma unroll
        for (int i = 0; i < 2; i++) {
            int r = brow + i * 8;
            *(float4*)&Bs[r][bcol] = *(const float4*)(W + (size_t)(k0 + r) * Dd + n0 + bcol);
        }
        __syncthreads();

#pragma unroll
        for (int kk = 0; kk < BK; kk++) {
            float ar[TM], br[TN];
#pragma unroll
            for (int i = 0; i < TM; i++) ar[i] = As[kk][tr + i];
#pragma unroll
            for (int j = 0; j < TN; j++) br[j] = Bs[kk][tc + j];
#pragma unroll
            for (int i = 0; i < TM; i++)
#pragma unroll
                for (int j = 0; j < TN; j++)
                    acc[i][j] = fmaf(ar[i], br[j], acc[i][j]);
        }
        __syncthreads();
    }

#pragma unroll
    for (int i = 0; i < TM; i++) {
        int gm = m0 + tr + i;
        if (gm >= Nn) continue;
#pragma unroll
        for (int j = 0; j < TN; j += 4) {
            int gc = n0 + tc + j;
            float4 hv = make_float4(acc[i][j], acc[i][j + 1], acc[i][j + 2], acc[i][j + 3]);
            *(float4*)(H + (size_t)gm * Dd + gc) = hv;
        }
    }
}

// One warp per destination node: OUT[c] = bias + dinv[c]^2*H[c] + sum_seg norm*H[row].
// Each lane accumulates float4 chunks q0=lane, q1=lane+32 (of 64 per row).
__global__ void __launch_bounds__(256)
k_aggregate(const int* __restrict__ ptr, const int* __restrict__ erow,
            const float* __restrict__ enorm, const float4* __restrict__ H,
            const float* __restrict__ dinv, const float4* __restrict__ bias,
            float4* __restrict__ OUT) {
    int warp = (blockIdx.x * blockDim.x + threadIdx.x) >> 5;
    int lane = threadIdx.x & 31;
    if (warp >= Nn) return;
    int node = warp;
    int q0 = lane, q1 = lane + 32;

    float s = dinv[node];
    s = s * s;
    const float4* hc = H + (size_t)node * D4;
    float4 hv0 = hc[q0], hv1 = hc[q1];
    float4 b0 = bias[q0], b1 = bias[q1];
    float4 acc0 = make_float4(fmaf(s, hv0.x, b0.x), fmaf(s, hv0.y, b0.y),
                              fmaf(s, hv0.z, b0.z), fmaf(s, hv0.w, b0.w));
    float4 acc1 = make_float4(fmaf(s, hv1.x, b1.x), fmaf(s, hv1.y, b1.y),
                              fmaf(s, hv1.z, b1.z), fmaf(s, hv1.w, b1.w));

    int jb = ptr[node], je = ptr[node + 1];
    for (int j = jb; j < je; j++) {
        int r = erow[j];
        float nm = enorm[j];
        const float4* hr = H + (size_t)r * D4;
        float4 v0 = hr[q0], v1 = hr[q1];
        acc0.x = fmaf(nm, v0.x, acc0.x); acc0.y = fmaf(nm, v0.y, acc0.y);
        acc0.z = fmaf(nm, v0.z, acc0.z); acc0.w = fmaf(nm, v0.w, acc0.w);
        acc1.x = fmaf(nm, v1.x, acc1.x); acc1.y = fmaf(nm, v1.y, acc1.y);
        acc1.z = fmaf(nm, v1.z, acc1.z); acc1.w = fmaf(nm, v1.w, acc1.w);
    }
    float4* op = OUT + (size_t)node * D4;
    op[q0] = acc0;
    op[q1] = acc1;
}

extern "C" void kernel_launch(void* const* d_in, const int* in_sizes, int n_in,
                              void* d_out, int out_size) {
    const int*   ids_all = (const int*)d_in[0];    // (T, N)
    const int*   ei_all  = (const int*)d_in[1];    // (T, 2, E)
    const float* w_all   = (const float*)d_in[2];  // (T, E)
    const float* emb     = (const float*)d_in[3];  // (VOCAB, D)
    const float* Ws[3] = {(const float*)d_in[4], (const float*)d_in[6], (const float*)d_in[8]};
    const float* bs[3] = {(const float*)d_in[5], (const float*)d_in[7], (const float*)d_in[9]};
    float* out = (float*)d_out;

    void *pa, *ph, *pb, *pd, *pc, *pu, *pp, *pe, *pm;
    cudaGetSymbolAddress(&pa, g_a);
    cudaGetSymbolAddress(&ph, g_h);
    cudaGetSymbolAddress(&pb, g_b);
    cudaGetSymbolAddress(&pd, g_dinv);
    cudaGetSymbolAddress(&pc, g_cnt);
    cudaGetSymbolAddress(&pu, g_cur);
    cudaGetSymbolAddress(&pp, g_ptr);
    cudaGetSymbolAddress(&pe, g_erow);
    cudaGetSymbolAddress(&pm, g_enorm);
    float* A    = (float*)pa;
    float* Hh   = (float*)ph;
    float* B    = (float*)pb;
    float* dinv = (float*)pd;
    int*   cnt  = (int*)pc;
    int*   cur  = (int*)pu;
    int*   ptr  = (int*)pp;
    int*   erow = (int*)pe;
    float* enrm = (float*)pm;

    const int TPB = 256;
    dim3 ggrid((Nn + 127) / 128, Dd / 128);
    int aggBlocks = (Nn * 32 + TPB - 1) / TPB;

    for (int t = 0; t < Tt; t++) {
        const int*   row  = ei_all + (size_t)t * 2 * Ee;
        const int*   col  = row + Ee;
        const float* w    = w_all + (size_t)t * Ee;
        const int*   ids  = ids_all + (size_t)t * Nn;
        float*       outT = out + (size_t)t * Nn * Dd;

        k_init<<<(Nn + TPB - 1) / TPB, TPB>>>(dinv, cnt);
        k_edge_prep<<<(Ee + TPB - 1) / TPB, TPB>>>(col, w, dinv, cnt);
        k_finalize_dinv<<<(Nn + TPB - 1) / TPB, TPB>>>(dinv);
        k_scan<<<1, 1024>>>(cnt, ptr, cur);
        k_permute<<<(Ee + TPB - 1) / TPB, TPB>>>(row, col, w, dinv, cur, erow, enrm);
        k_gather<<<(Nn * D4 + TPB - 1) / TPB, TPB>>>(ids, (const float4*)emb, (float4*)A);

        struct { const float* X; float* OUT; } io[3] = {{A, B}, {B, A}, {A, outT}};
        for (int l = 0; l < 3; l++) {
            k_gemm<<<ggrid, 256>>>(io[l].X, Ws[l], Hh);
            k_aggregate<<<aggBlocks, TPB>>>(ptr, erow, enrm, (const float4*)Hh,
                                            dinv, (const float4*)bs[l],
                                            (float4*)io[l].OUT);
        }
    }
}

// round 4
// speedup vs baseline: 1.9661x; 1.5830x over previous
#include <cuda_runtime.h>
#include <cuda_bf16.h>
#include <cstdint>

#define Tt 4
#define Nn 50000
#define Ee 800000
#define Dd 256
#define D4 64   // Dd/4

// ---------------- scratch (device globals; no allocation) ----------------
__device__ float          g_h[(size_t)Nn * Dd];          // GEMM output (fp32)
__device__ __nv_bfloat16  g_xh[(size_t)Nn * Dd];         // X split hi
__device__ __nv_bfloat16  g_xl[(size_t)Nn * Dd];         // X split lo
__device__ __nv_bfloat16  g_wh[3][Dd * Dd];              // W^T split hi  [N,K]
__device__ __nv_bfloat16  g_wl[3][Dd * Dd];              // W^T split lo  [N,K]
__device__ float g_dinv[Nn];
__device__ int   g_cnt[Nn];
__device__ int   g_cur[Nn];
__device__ int   g_ptr[Nn + 1];
__device__ int   g_erow[Ee];
__device__ float g_enorm[Ee];

// ---------------- small helpers ----------------
__device__ __forceinline__ uint32_t pack2(float a, float b) {
    __nv_bfloat162 t;
    t.x = __float2bfloat16_rn(a);
    t.y = __float2bfloat16_rn(b);
    return *reinterpret_cast<uint32_t*>(&t);
}
struct B4 { uint2 hi, lo; };
__device__ __forceinline__ B4 split4(float4 v) {
    __nv_bfloat16 ha = __float2bfloat16_rn(v.x), hb = __float2bfloat16_rn(v.y);
    __nv_bfloat16 hc = __float2bfloat16_rn(v.z), hd = __float2bfloat16_rn(v.w);
    float ra = v.x - __bfloat162float(ha), rb = v.y - __bfloat162float(hb);
    float rc = v.z - __bfloat162float(hc), rd = v.w - __bfloat162float(hd);
    B4 o;
    __nv_bfloat162 t0; t0.x = ha; t0.y = hb;
    __nv_bfloat162 t1; t1.x = hc; t1.y = hd;
    o.hi.x = *reinterpret_cast<uint32_t*>(&t0);
    o.hi.y = *reinterpret_cast<uint32_t*>(&t1);
    o.lo.x = pack2(ra, rb);
    o.lo.y = pack2(rc, rd);
    return o;
}

// ---------------- prep kernels ----------------
__global__ void k_init(float* __restrict__ deg, int* __restrict__ cnt) {
    int i = blockIdx.x * blockDim.x + threadIdx.x;
    if (i < Nn) { deg[i] = 1.0f; cnt[i] = 0; }
}
__global__ void k_edge_prep(const int* __restrict__ col, const float* __restrict__ w,
                            float* __restrict__ deg, int* __restrict__ cnt) {
    int e = blockIdx.x * blockDim.x + threadIdx.x;
    if (e < Ee) {
        int c = col[e];
        atomicAdd(&deg[c], w[e]);
        atomicAdd(&cnt[c], 1);
    }
}
__global__ void k_finalize_dinv(float* __restrict__ deg) {
    int i = blockIdx.x * blockDim.x + threadIdx.x;
    if (i < Nn) {
        float d = deg[i];
        deg[i] = (d > 0.0f) ? rsqrtf(d) : 0.0f;
    }
}

// single-block scan, 4 elems/thread (13 iterations over 50000)
__global__ void __launch_bounds__(1024)
k_scan(const int* __restrict__ cnt, int* __restrict__ ptr, int* __restrict__ cur) {
    __shared__ int wt[32];
    __shared__ int carry_sh;
    int tid = threadIdx.x, lane = tid & 31, wid = tid >> 5;
    if (tid == 0) { carry_sh = 0; ptr[0] = 0; }
    __syncthreads();
    for (int base = 0; base < Nn; base += 4096) {
        int i0 = base + tid * 4;
        int4 v = make_int4(0, 0, 0, 0);
        if (i0 + 3 < Nn) v = *(const int4*)(cnt + i0);
        else {
            if (i0 < Nn)     v.x = cnt[i0];
            if (i0 + 1 < Nn) v.y = cnt[i0 + 1];
            if (i0 + 2 < Nn) v.z = cnt[i0 + 2];
        }
        int tsum = v.x + v.y + v.z + v.w;
        int s = tsum;
#pragma unroll
        for (int off = 1; off < 32; off <<= 1) {
            int t = __shfl_up_sync(0xffffffffu, s, off);
            if (lane >= off) s += t;
        }
        if (lane == 31) wt[wid] = s;
        __syncthreads();
        if (wid == 0) {
            int ws = wt[lane];
#pragma unroll
            for (int off = 1; off < 32; off <<= 1) {
                int t = __shfl_up_sync(0xffffffffu, ws, off);
                if (lane >= off) ws += t;
            }
            wt[lane] = ws;
        }
        __syncthreads();
        int excl = s - tsum + (wid > 0 ? wt[wid - 1] : 0) + carry_sh;
        int p = excl;
        if (i0 < Nn)     { cur[i0] = p;     ptr[i0 + 1] = p + v.x; } p += v.x;
        if (i0 + 1 < Nn) { cur[i0 + 1] = p; ptr[i0 + 2] = p + v.y; } p += v.y;
        if (i0 + 2 < Nn) { cur[i0 + 2] = p; ptr[i0 + 3] = p + v.z; } p += v.z;
        if (i0 + 3 < Nn) { cur[i0 + 3] = p; ptr[i0 + 4] = p + v.w; }
        __syncthreads();
        if (tid == 1023) carry_sh = excl + tsum;
        __syncthreads();
    }
}

__global__ void k_permute(const int* __restrict__ row, const int* __restrict__ col,
                          const float* __restrict__ w, const float* __restrict__ dinv,
                          int* __restrict__ cur, int* __restrict__ erow,
                          float* __restrict__ enorm) {
    int e = blockIdx.x * blockDim.x + threadIdx.x;
    if (e < Ee) {
        int r = row[e], c = col[e];
        float nm = dinv[r] * w[e] * dinv[c];
        int pos = atomicAdd(&cur[c], 1);
        erow[pos] = r;
        enorm[pos] = nm;
    }
}

// W^T split: wh/wl[n*256+k] = split(W[k*256+n])
__global__ void k_wprep(const float* __restrict__ W, __nv_bfloat16* __restrict__ wh,
                        __nv_bfloat16* __restrict__ wl) {
    int idx = blockIdx.x * blockDim.x + threadIdx.x;
    if (idx < Dd * Dd) {
        int n = idx >> 8, k = idx & 255;
        float w = W[k * Dd + n];
        __nv_bfloat16 h = __float2bfloat16_rn(w);
        wh[idx] = h;
        wl[idx] = __float2bfloat16_rn(w - __bfloat162float(h));
    }
}

// embedding gather -> bf16 splits
__global__ void k_gather(const int* __restrict__ ids, const float4* __restrict__ emb,
                         uint2* __restrict__ xh, uint2* __restrict__ xl) {
    int idx = blockIdx.x * blockDim.x + threadIdx.x;
    if (idx < Nn * D4) {
        int i = idx >> 6, q = idx & 63;
        float4 v = emb[(size_t)ids[i] * D4 + q];
        B4 s = split4(v);
        xh[idx] = s.hi;
        xl[idx] = s.lo;
    }
}

// ---------------- mma.sync bf16 GEMM: H[Nn,256] = X @ W ----------------
// Virtual K' = 3*256: (xh,Wh), (xh,Wl), (xl,Wh).  CTA tile 128x128x32.
// smem tiles [128][32] bf16 with 16B-chunk swizzle c' = c ^ ((row>>1)&3).
__device__ __forceinline__ uint32_t swz(int row, int c) {
    return (uint32_t)(row * 64 + ((c ^ ((row >> 1) & 3)) << 4));
}

__global__ void __launch_bounds__(256, 2)
k_gemm_mma(const __nv_bfloat16* __restrict__ xh, const __nv_bfloat16* __restrict__ xl,
           const __nv_bfloat16* __restrict__ wh, const __nv_bfloat16* __restrict__ wl,
           float* __restrict__ H) {
    __shared__ __align__(128) char sA[2][8192];
    __shared__ __align__(128) char sB[2][8192];

    const int tid = threadIdx.x;
    const int wid = tid >> 5, lane = tid & 31;
    const int m0 = blockIdx.x * 128, n0 = blockIdx.y * 128;
    const int mw = wid >> 2, nw = wid & 3;   // warp grid 2(M) x 4(N)

    const __nv_bfloat16* Asrc[3] = {xh, xh, xl};
    const __nv_bfloat16* Bsrc[3] = {wh, wl, wh};

    float acc[4][4][4] = {};

    auto issue = [&](int it, int buf) {
        int p = it >> 3, kc = (it & 7) * 32;
        const __nv_bfloat16* A = Asrc[p];
        const __nv_bfloat16* B = Bsrc[p];
#pragma unroll
        for (int i = 0; i < 2; i++) {
            int u = tid + i * 256;
            int row = u >> 2, c = u & 3;
            uint32_t dst = (uint32_t)__cvta_generic_to_shared(&sA[buf][swz(row, c)]);
            int gm = m0 + row;
            int ok = (gm < Nn);
            const void* src = A + (size_t)(ok ? gm : 0) * Dd + kc + c * 8;
            int sz = ok ? 16 : 0;
            asm volatile("cp.async.ca.shared.global [%0], [%1], 16, %2;"
                         :: "r"(dst), "l"(src), "r"(sz));
        }
#pragma unroll
        for (int i = 0; i < 2; i++) {
            int u = tid + i * 256;
            int row = u >> 2, c = u & 3;
            uint32_t dst = (uint32_t)__cvta_generic_to_shared(&sB[buf][swz(row, c)]);
            const void* src = B + (size_t)(n0 + row) * Dd + kc + c * 8;
            asm volatile("cp.async.ca.shared.global [%0], [%1], 16;"
                         :: "r"(dst), "l"(src));
        }
        asm volatile("cp.async.commit_group;");
    };

    issue(0, 0);
    for (int it = 0; it < 24; it++) {
        int buf = it & 1;
        if (it + 1 < 24) {
            issue(it + 1, buf ^ 1);
            asm volatile("cp.async.wait_group 1;");
        } else {
            asm volatile("cp.async.wait_group 0;");
        }
        __syncthreads();

#pragma unroll
        for (int ks = 0; ks < 2; ks++) {
            uint32_t af[4][4];
#pragma unroll
            for (int mt = 0; mt < 4; mt++) {
                int row = mw * 64 + mt * 16 + (lane & 15);
                int c = ks * 2 + ((lane >> 4) & 1);
                uint32_t addr = (uint32_t)__cvta_generic_to_shared(&sA[buf][swz(row, c)]);
                asm volatile("ldmatrix.sync.aligned.m8n8.x4.shared.b16 {%0,%1,%2,%3}, [%4];"
                             : "=r"(af[mt][0]), "=r"(af[mt][1]),
                               "=r"(af[mt][2]), "=r"(af[mt][3]) : "r"(addr));
            }
            uint32_t bf[4][2];
#pragma unroll
            for (int ntp = 0; ntp < 2; ntp++) {
                int row = nw * 32 + ntp * 16 + (lane & 7) + ((lane & 16) ? 8 : 0);
                int c = ks * 2 + ((lane & 8) ? 1 : 0);
                uint32_t addr = (uint32_t)__cvta_generic_to_shared(&sB[buf][swz(row, c)]);
                uint32_t r0, r1, r2, r3;
                asm volatile("ldmatrix.sync.aligned.m8n8.x4.shared.b16 {%0,%1,%2,%3}, [%4];"
                             : "=r"(r0), "=r"(r1), "=r"(r2), "=r"(r3) : "r"(addr));
                bf[ntp * 2][0] = r0; bf[ntp * 2][1] = r1;
                bf[ntp * 2 + 1][0] = r2; bf[ntp * 2 + 1][1] = r3;
            }
#pragma unroll
            for (int mt = 0; mt < 4; mt++)
#pragma unroll
                for (int nt = 0; nt < 4; nt++) {
                    asm volatile(
                        "mma.sync.aligned.m16n8k16.row.col.f32.bf16.bf16.f32 "
                        "{%0,%1,%2,%3}, {%4,%5,%6,%7}, {%8,%9}, {%0,%1,%2,%3};"
                        : "+f"(acc[mt][nt][0]), "+f"(acc[mt][nt][1]),
                          "+f"(acc[mt][nt][2]), "+f"(acc[mt][nt][3])
                        : "r"(af[mt][0]), "r"(af[mt][1]), "r"(af[mt][2]), "r"(af[mt][3]),
                          "r"(bf[nt][0]), "r"(bf[nt][1]));
                }
        }
        __syncthreads();
    }

#pragma unroll
    for (int mt = 0; mt < 4; mt++) {
        int mm = m0 + mw * 64 + mt * 16 + (lane >> 2);
#pragma unroll
        for (int nt = 0; nt < 4; nt++) {
            int cc = n0 + nw * 32 + nt * 8 + 2 * (lane & 3);
            if (mm < Nn)
                *(float2*)(H + (size_t)mm * Dd + cc) =
                    make_float2(acc[mt][nt][0], acc[mt][nt][1]);
            if (mm + 8 < Nn)
                *(float2*)(H + (size_t)(mm + 8) * Dd + cc) =
                    make_float2(acc[mt][nt][2], acc[mt][nt][3]);
        }
    }
}

// ---------------- aggregate: one warp per destination node ----------------
__global__ void __launch_bounds__(256)
k_aggregate(const int* __restrict__ ptr, const int* __restrict__ erow,
            const float* __restrict__ enorm, const float4* __restrict__ H,
            const float* __restrict__ dinv, const float4* __restrict__ bias,
            float4* __restrict__ outF, uint2* __restrict__ oxh, uint2* __restrict__ oxl) {
    int warp = (blockIdx.x * blockDim.x + threadIdx.x) >> 5;
    int lane = threadIdx.x & 31;
    if (warp >= Nn) return;
    int node = warp;
    int q0 = lane, q1 = lane + 32;

    float s = dinv[node];
    s = s * s;
    const float4* hc = H + (size_t)node * D4;
    float4 hv0 = hc[q0], hv1 = hc[q1];
    float4 b0 = bias[q0], b1 = bias[q1];
    float4 acc0 = make_float4(fmaf(s, hv0.x, b0.x), fmaf(s, hv0.y, b0.y),
                              fmaf(s, hv0.z, b0.z), fmaf(s, hv0.w, b0.w));
    float4 acc1 = make_float4(fmaf(s, hv1.x, b1.x), fmaf(s, hv1.y, b1.y),
                              fmaf(s, hv1.z, b1.z), fmaf(s, hv1.w, b1.w));

    int jb = ptr[node], je = ptr[node + 1];
    for (int j = jb; j < je; j++) {
        int r = erow[j];
        float nm = enorm[j];
        const float4* hr = H + (size_t)r * D4;
        float4 v0 = hr[q0], v1 = hr[q1];
        acc0.x = fmaf(nm, v0.x, acc0.x); acc0.y = fmaf(nm, v0.y, acc0.y);
        acc0.z = fmaf(nm, v0.z, acc0.z); acc0.w = fmaf(nm, v0.w, acc0.w);
        acc1.x = fmaf(nm, v1.x, acc1.x); acc1.y = fmaf(nm, v1.y, acc1.y);
        acc1.z = fmaf(nm, v1.z, acc1.z); acc1.w = fmaf(nm, v1.w, acc1.w);
    }
    if (outF) {
        float4* op = outF + (size_t)node * D4;
        op[q0] = acc0;
        op[q1] = acc1;
    }
    if (oxh) {
        B4 s0 = split4(acc0), s1 = split4(acc1);
        uint2* ph = oxh + (size_t)node * D4;
        uint2* pl = oxl + (size_t)node * D4;
        ph[q0] = s0.hi; ph[q1] = s1.hi;
        pl[q0] = s0.lo; pl[q1] = s1.lo;
    }
}

// ---------------- launch ----------------
extern "C" void kernel_launch(void* const* d_in, const int* in_sizes, int n_in,
                              void* d_out, int out_size) {
    const int*   ids_all = (const int*)d_in[0];
    const int*   ei_all  = (const int*)d_in[1];
    const float* w_all   = (const float*)d_in[2];
    const float* emb     = (const float*)d_in[3];
    const float* Ws[3] = {(const float*)d_in[4], (const float*)d_in[6], (const float*)d_in[8]};
    const float* bs[3] = {(const float*)d_in[5], (const float*)d_in[7], (const float*)d_in[9]};
    float* out = (float*)d_out;

    void *ph, *pxh, *pxl, *pwh, *pwl, *pd, *pc, *pu, *pp, *pe, *pm;
    cudaGetSymbolAddress(&ph,  g_h);
    cudaGetSymbolAddress(&pxh, g_xh);
    cudaGetSymbolAddress(&pxl, g_xl);
    cudaGetSymbolAddress(&pwh, g_wh);
    cudaGetSymbolAddress(&pwl, g_wl);
    cudaGetSymbolAddress(&pd,  g_dinv);
    cudaGetSymbolAddress(&pc,  g_cnt);
    cudaGetSymbolAddress(&pu,  g_cur);
    cudaGetSymbolAddress(&pp,  g_ptr);
    cudaGetSymbolAddress(&pe,  g_erow);
    cudaGetSymbolAddress(&pm,  g_enorm);
    float* Hh = (float*)ph;
    __nv_bfloat16* xh = (__nv_bfloat16*)pxh;
    __nv_bfloat16* xl = (__nv_bfloat16*)pxl;
    __nv_bfloat16* wh = (__nv_bfloat16*)pwh;
    __nv_bfloat16* wl = (__nv_bfloat16*)pwl;
    float* dinv = (float*)pd;
    int* cnt = (int*)pc;
    int* cur = (int*)pu;
    int* ptr = (int*)pp;
    int* erow = (int*)pe;
    float* enrm = (float*)pm;

    const int TPB = 256;

    for (int l = 0; l < 3; l++)
        k_wprep<<<(Dd * Dd + TPB - 1) / TPB, TPB>>>(Ws[l], wh + (size_t)l * Dd * Dd,
                                                    wl + (size_t)l * Dd * Dd);

    int aggBlocks = (Nn * 32 + TPB - 1) / TPB;
    dim3 ggrid((Nn + 127) / 128, Dd / 128);

    for (int t = 0; t < Tt; t++) {
        const int*   row  = ei_all + (size_t)t * 2 * Ee;
        const int*   col  = row + Ee;
        const float* w    = w_all + (size_t)t * Ee;
        const int*   ids  = ids_all + (size_t)t * Nn;
        float*       outT = out + (size_t)t * Nn * Dd;

        k_init<<<(Nn + TPB - 1) / TPB, TPB>>>(dinv, cnt);
        k_edge_prep<<<(Ee + TPB - 1) / TPB, TPB>>>(col, w, dinv, cnt);
        k_finalize_dinv<<<(Nn + TPB - 1) / TPB, TPB>>>(dinv);
        k_scan<<<1, 1024>>>(cnt, ptr, cur);
        k_permute<<<(Ee + TPB - 1) / TPB, TPB>>>(row, col, w, dinv, cur, erow, enrm);
        k_gather<<<(Nn * D4 + TPB - 1) / TPB, TPB>>>(ids, (const float4*)emb,
                                                     (uint2*)xh, (uint2*)xl);

        for (int l = 0; l < 3; l++) {
            k_gemm_mma<<<ggrid, 256>>>(xh, xl,
                                       wh + (size_t)l * Dd * Dd,
                                       wl + (size_t)l * Dd * Dd, Hh);
            bool last = (l == 2);
            k_aggregate<<<aggBlocks, TPB>>>(ptr, erow, enrm, (const float4*)Hh,
                                            dinv, (const float4*)bs[l],
                                            last ? (float4*)outT : (float4*)nullptr,
                                            last ? (uint2*)nullptr : (uint2*)xh,
                                            last ? (uint2*)nullptr : (uint2*)xl);
        }
    }
}

// round 5
// speedup vs baseline: 2.5039x; 1.2735x over previous
#include <cuda_runtime.h>
#include <cuda_bf16.h>
#include <cstdint>

#define Tt 4
#define Nn 50000
#define Ee 800000
#define Dd 256
#define D4 64
#define NT (Tt * Nn)        // 200000
#define ET (Tt * Ee)        // 3200000
#define SCAN_BLK 49         // ceil(200000/4096)

// ---------------- scratch ----------------
__device__ float          g_h[(size_t)Nn * Dd];
__device__ __nv_bfloat16  g_xh[(size_t)NT * Dd];
__device__ __nv_bfloat16  g_xl[(size_t)NT * Dd];
__device__ __nv_bfloat16  g_wh[3][Dd * Dd];
__device__ __nv_bfloat16  g_wl[3][Dd * Dd];
__device__ float g_dinv[NT];
__device__ int   g_cnt[NT];
__device__ int   g_cur[NT];
__device__ int   g_ptr[NT + 1];
__device__ int   g_bsum[64];
__device__ int   g_boff[64];
__device__ int   g_erow[ET];
__device__ float g_enorm[ET];

// ---------------- helpers ----------------
__device__ __forceinline__ uint32_t pack2(float a, float b) {
    __nv_bfloat162 t;
    t.x = __float2bfloat16_rn(a);
    t.y = __float2bfloat16_rn(b);
    return *reinterpret_cast<uint32_t*>(&t);
}
struct B4 { uint2 hi, lo; };
__device__ __forceinline__ B4 split4(float4 v) {
    __nv_bfloat16 ha = __float2bfloat16_rn(v.x), hb = __float2bfloat16_rn(v.y);
    __nv_bfloat16 hc = __float2bfloat16_rn(v.z), hd = __float2bfloat16_rn(v.w);
    float ra = v.x - __bfloat162float(ha), rb = v.y - __bfloat162float(hb);
    float rc = v.z - __bfloat162float(hc), rd = v.w - __bfloat162float(hd);
    B4 o;
    __nv_bfloat162 t0; t0.x = ha; t0.y = hb;
    __nv_bfloat162 t1; t1.x = hc; t1.y = hd;
    o.hi.x = *reinterpret_cast<uint32_t*>(&t0);
    o.hi.y = *reinterpret_cast<uint32_t*>(&t1);
    o.lo.x = pack2(ra, rb);
    o.lo.y = pack2(rc, rd);
    return o;
}

// ---------------- batched prep (block-diagonal 4-timestep graph) ----------------
__global__ void k_init(float* __restrict__ deg, int* __restrict__ cnt) {
    int i = blockIdx.x * blockDim.x + threadIdx.x;
    if (i < NT) { deg[i] = 1.0f; cnt[i] = 0; }
}

__global__ void k_edge_prep(const int* __restrict__ ei_all, const float* __restrict__ w_all,
                            float* __restrict__ deg, int* __restrict__ cnt) {
    int ge = blockIdx.x * blockDim.x + threadIdx.x;
    if (ge < ET) {
        int t = ge / Ee, e = ge - t * Ee;
        int c = ei_all[(size_t)t * 2 * Ee + Ee + e];
        int gc = t * Nn + c;
        atomicAdd(&deg[gc], w_all[ge]);
        atomicAdd(&cnt[gc], 1);
    }
}

__global__ void k_finalize_dinv(float* __restrict__ deg) {
    int i = blockIdx.x * blockDim.x + threadIdx.x;
    if (i < NT) {
        float d = deg[i];
        deg[i] = (d > 0.0f) ? rsqrtf(d) : 0.0f;
    }
}

// Phase 1: per-block (4096 elems) local scan. cur=local excl, ptr[i+1]=local incl.
__global__ void __launch_bounds__(1024)
k_scan1(const int* __restrict__ cnt, int* __restrict__ ptr, int* __restrict__ cur,
        int* __restrict__ bsum) {
    __shared__ int wt[32];
    int tid = threadIdx.x, lane = tid & 31, wid = tid >> 5;
    int i0 = blockIdx.x * 4096 + tid * 4;
    int4 v = make_int4(0, 0, 0, 0);
    if (i0 + 3 < NT) v = *(const int4*)(cnt + i0);
    else {
        if (i0 < NT)     v.x = cnt[i0];
        if (i0 + 1 < NT) v.y = cnt[i0 + 1];
        if (i0 + 2 < NT) v.z = cnt[i0 + 2];
    }
    int tsum = v.x + v.y + v.z + v.w;
    int s = tsum;
#pragma unroll
    for (int off = 1; off < 32; off <<= 1) {
        int t = __shfl_up_sync(0xffffffffu, s, off);
        if (lane >= off) s += t;
    }
    if (lane == 31) wt[wid] = s;
    __syncthreads();
    if (wid == 0) {
        int ws = wt[lane];
#pragma unroll
        for (int off = 1; off < 32; off <<= 1) {
            int t = __shfl_up_sync(0xffffffffu, ws, off);
            if (lane >= off) ws += t;
        }
        wt[lane] = ws;
    }
    __syncthreads();
    int excl = s - tsum + (wid > 0 ? wt[wid - 1] : 0);
    int p = excl;
    if (i0 < NT)     { cur[i0] = p;     ptr[i0 + 1] = p + v.x; } p += v.x;
    if (i0 + 1 < NT) { cur[i0 + 1] = p; ptr[i0 + 2] = p + v.y; } p += v.y;
    if (i0 + 2 < NT) { cur[i0 + 2] = p; ptr[i0 + 3] = p + v.z; } p += v.z;
    if (i0 + 3 < NT) { cur[i0 + 3] = p; ptr[i0 + 4] = p + v.w; }
    if (tid == 1023) bsum[blockIdx.x] = excl + tsum;
}

// Phase 2: scan block totals (tiny).
__global__ void k_scan2(const int* __restrict__ bsum, int* __restrict__ boff,
                        int* __restrict__ ptr) {
    if (threadIdx.x == 0) {
        ptr[0] = 0;
        int run = 0;
        for (int b = 0; b < SCAN_BLK; b++) { boff[b] = run; run += bsum[b]; }
    }
}

// Phase 3: add block offsets.
__global__ void __launch_bounds__(1024)
k_scan3(const int* __restrict__ boff, int* __restrict__ ptr, int* __restrict__ cur) {
    int off = boff[blockIdx.x];
    int i0 = blockIdx.x * 4096 + threadIdx.x * 4;
#pragma unroll
    for (int k = 0; k < 4; k++) {
        int i = i0 + k;
        if (i < NT) { cur[i] += off; ptr[i + 1] += off; }
    }
}

__global__ void k_permute(const int* __restrict__ ei_all, const float* __restrict__ w_all,
                          const float* __restrict__ dinv, int* __restrict__ cur,
                          int* __restrict__ erow, float* __restrict__ enorm) {
    int ge = blockIdx.x * blockDim.x + threadIdx.x;
    if (ge < ET) {
        int t = ge / Ee, e = ge - t * Ee;
        const int* base = ei_all + (size_t)t * 2 * Ee;
        int r = base[e], c = base[Ee + e];
        int gr = t * Nn + r, gc = t * Nn + c;
        float nm = dinv[gr] * w_all[ge] * dinv[gc];
        int pos = atomicAdd(&cur[gc], 1);
        erow[pos] = r;          // local row within timestep
        enorm[pos] = nm;
    }
}

__global__ void k_wprep(const float* __restrict__ W, __nv_bfloat16* __restrict__ wh,
                        __nv_bfloat16* __restrict__ wl) {
    int idx = blockIdx.x * blockDim.x + threadIdx.x;
    if (idx < Dd * Dd) {
        int n = idx >> 8, k = idx & 255;
        float w = W[k * Dd + n];
        __nv_bfloat16 h = __float2bfloat16_rn(w);
        wh[idx] = h;
        wl[idx] = __float2bfloat16_rn(w - __bfloat162float(h));
    }
}

// batched gather over all 4 timesteps
__global__ void k_gather(const int* __restrict__ ids, const float4* __restrict__ emb,
                         uint2* __restrict__ xh, uint2* __restrict__ xl) {
    int idx = blockIdx.x * blockDim.x + threadIdx.x;
    if (idx < NT * D4) {
        int i = idx >> 6, q = idx & 63;
        float4 v = emb[(size_t)ids[i] * D4 + q];
        B4 s = split4(v);
        xh[idx] = s.hi;
        xl[idx] = s.lo;
    }
}

// ---------------- mma.sync bf16 GEMM (restructured: 8 stages x 3 products) ----------
__device__ __forceinline__ uint32_t swz(int row, int c) {
    return (uint32_t)(row * 64 + ((c ^ ((row >> 1) & 3)) << 4));
}

#define GEMM_SMEM 65536   // 2 stages x 4 tiles x 8KB

__global__ void __launch_bounds__(256)
k_gemm_mma(const __nv_bfloat16* __restrict__ xh, const __nv_bfloat16* __restrict__ xl,
           const __nv_bfloat16* __restrict__ wh, const __nv_bfloat16* __restrict__ wl,
           float* __restrict__ H) {
    extern __shared__ __align__(128) char sm[];

    const int tid = threadIdx.x;
    const int wid = tid >> 5, lane = tid & 31;
    const int m0 = blockIdx.x * 128, n0 = blockIdx.y * 128;
    const int mw = wid >> 2, nw = wid & 3;

    float acc[4][4][4] = {};

    auto issue = [&](int kc, int stage) {
        char* sbase = sm + stage * 32768;
#pragma unroll
        for (int i = 0; i < 8; i++) {
            int u = tid + i * 256;
            int tile = u >> 9, idx = u & 511;
            int row = idx >> 2, c = idx & 3;
            uint32_t dst = (uint32_t)__cvta_generic_to_shared(
                sbase + tile * 8192 + swz(row, c));
            if (tile < 2) {
                const __nv_bfloat16* A = (tile == 0) ? xh : xl;
                int gm = m0 + row;
                int ok = (gm < Nn);
                const void* src = A + (size_t)(ok ? gm : 0) * Dd + kc * 32 + c * 8;
                int sz = ok ? 16 : 0;
                asm volatile("cp.async.ca.shared.global [%0], [%1], 16, %2;"
                             :: "r"(dst), "l"(src), "r"(sz));
            } else {
                const __nv_bfloat16* B = (tile == 2) ? wh : wl;
                const void* src = B + (size_t)(n0 + row) * Dd + kc * 32 + c * 8;
                asm volatile("cp.async.ca.shared.global [%0], [%1], 16;"
                             :: "r"(dst), "l"(src));
            }
        }
        asm volatile("cp.async.commit_group;");
    };

    issue(0, 0);
    for (int it = 0; it < 8; it++) {
        int buf = it & 1;
        if (it + 1 < 8) {
            issue(it + 1, buf ^ 1);
            asm volatile("cp.async.wait_group 1;");
        } else {
            asm volatile("cp.async.wait_group 0;");
        }
        __syncthreads();
        char* pAh = sm + buf * 32768;
        char* pAl = pAh + 8192;
        char* pBh = pAh + 16384;
        char* pBl = pAh + 24576;

#pragma unroll
        for (int ks = 0; ks < 2; ks++) {
            int arow_c = ks * 2 + ((lane >> 4) & 1);
            int brow = ((lane & 7) + ((lane & 16) ? 8 : 0));
            int bc = ks * 2 + ((lane & 8) ? 1 : 0);
            uint32_t afh[4][4], afl[4][4];
#pragma unroll
            for (int mt = 0; mt < 4; mt++) {
                int row = mw * 64 + mt * 16 + (lane & 15);
                uint32_t ah = (uint32_t)__cvta_generic_to_shared(pAh + swz(row, arow_c));
                uint32_t al = (uint32_t)__cvta_generic_to_shared(pAl + swz(row, arow_c));
                asm volatile("ldmatrix.sync.aligned.m8n8.x4.shared.b16 {%0,%1,%2,%3}, [%4];"
                             : "=r"(afh[mt][0]), "=r"(afh[mt][1]),
                               "=r"(afh[mt][2]), "=r"(afh[mt][3]) : "r"(ah));
                asm volatile("ldmatrix.sync.aligned.m8n8.x4.shared.b16 {%0,%1,%2,%3}, [%4];"
                             : "=r"(afl[mt][0]), "=r"(afl[mt][1]),
                               "=r"(afl[mt][2]), "=r"(afl[mt][3]) : "r"(al));
            }
            uint32_t bfh[4][2], bfl[4][2];
#pragma unroll
            for (int ntp = 0; ntp < 2; ntp++) {
                int row = nw * 32 + ntp * 16 + brow;
                uint32_t bh = (uint32_t)__cvta_generic_to_shared(pBh + swz(row, bc));
                uint32_t bl = (uint32_t)__cvta_generic_to_shared(pBl + swz(row, bc));
                uint32_t r0, r1, r2, r3;
                asm volatile("ldmatrix.sync.aligned.m8n8.x4.shared.b16 {%0,%1,%2,%3}, [%4];"
                             : "=r"(r0), "=r"(r1), "=r"(r2), "=r"(r3) : "r"(bh));
                bfh[ntp * 2][0] = r0; bfh[ntp * 2][1] = r1;
                bfh[ntp * 2 + 1][0] = r2; bfh[ntp * 2 + 1][1] = r3;
                asm volatile("ldmatrix.sync.aligned.m8n8.x4.shared.b16 {%0,%1,%2,%3}, [%4];"
                             : "=r"(r0), "=r"(r1), "=r"(r2), "=r"(r3) : "r"(bl));
                bfl[ntp * 2][0] = r0; bfl[ntp * 2][1] = r1;
                bfl[ntp * 2 + 1][0] = r2; bfl[ntp * 2 + 1][1] = r3;
            }
#define MMA(af, bf) \
    asm volatile("mma.sync.aligned.m16n8k16.row.col.f32.bf16.bf16.f32 " \
                 "{%0,%1,%2,%3}, {%4,%5,%6,%7}, {%8,%9}, {%0,%1,%2,%3};" \
                 : "+f"(acc[mt][nt][0]), "+f"(acc[mt][nt][1]), \
                   "+f"(acc[mt][nt][2]), "+f"(acc[mt][nt][3]) \
                 : "r"(af[mt][0]), "r"(af[mt][1]), "r"(af[mt][2]), "r"(af[mt][3]), \
                   "r"(bf[nt][0]), "r"(bf[nt][1]))
#pragma unroll
            for (int mt = 0; mt < 4; mt++)
#pragma unroll
                for (int nt = 0; nt < 4; nt++) {
                    MMA(afh, bfh);
                    MMA(afh, bfl);
                    MMA(afl, bfh);
                }
#undef MMA
        }
        __syncthreads();
    }

#pragma unroll
    for (int mt = 0; mt < 4; mt++) {
        int mm = m0 + mw * 64 + mt * 16 + (lane >> 2);
#pragma unroll
        for (int nt = 0; nt < 4; nt++) {
            int cc = n0 + nw * 32 + nt * 8 + 2 * (lane & 3);
            if (mm < Nn)
                *(float2*)(H + (size_t)mm * Dd + cc) =
                    make_float2(acc[mt][nt][0], acc[mt][nt][1]);
            if (mm + 8 < Nn)
                *(float2*)(H + (size_t)(mm + 8) * Dd + cc) =
                    make_float2(acc[mt][nt][2], acc[mt][nt][3]);
        }
    }
}

// ---------------- aggregate: one warp per destination node (x2 unrolled) --------
__global__ void __launch_bounds__(256)
k_aggregate(const int* __restrict__ ptr, const int* __restrict__ erow,
            const float* __restrict__ enorm, const float4* __restrict__ H,
            const float* __restrict__ dinv, const float4* __restrict__ bias,
            float4* __restrict__ outF, uint2* __restrict__ oxh, uint2* __restrict__ oxl) {
    int warp = (blockIdx.x * blockDim.x + threadIdx.x) >> 5;
    int lane = threadIdx.x & 31;
    if (warp >= Nn) return;
    int node = warp;
    int q0 = lane, q1 = lane + 32;

    float s = dinv[node];
    s = s * s;
    const float4* hc = H + (size_t)node * D4;
    float4 hv0 = hc[q0], hv1 = hc[q1];
    float4 b0 = bias[q0], b1 = bias[q1];
    float4 acc0 = make_float4(fmaf(s, hv0.x, b0.x), fmaf(s, hv0.y, b0.y),
                              fmaf(s, hv0.z, b0.z), fmaf(s, hv0.w, b0.w));
    float4 acc1 = make_float4(fmaf(s, hv1.x, b1.x), fmaf(s, hv1.y, b1.y),
                              fmaf(s, hv1.z, b1.z), fmaf(s, hv1.w, b1.w));

    int jb = ptr[node], je = ptr[node + 1];
    int j = jb;
    for (; j + 1 < je; j += 2) {
        int ra = erow[j], rb = erow[j + 1];
        float na = enorm[j], nb = enorm[j + 1];
        const float4* ha = H + (size_t)ra * D4;
        const float4* hb = H + (size_t)rb * D4;
        float4 a0 = ha[q0], a1 = ha[q1];
        float4 c0 = hb[q0], c1 = hb[q1];
        acc0.x = fmaf(na, a0.x, acc0.x); acc0.y = fmaf(na, a0.y, acc0.y);
        acc0.z = fmaf(na, a0.z, acc0.z); acc0.w = fmaf(na, a0.w, acc0.w);
        acc1.x = fmaf(na, a1.x, acc1.x); acc1.y = fmaf(na, a1.y, acc1.y);
        acc1.z = fmaf(na, a1.z, acc1.z); acc1.w = fmaf(na, a1.w, acc1.w);
        acc0.x = fmaf(nb, c0.x, acc0.x); acc0.y = fmaf(nb, c0.y, acc0.y);
        acc0.z = fmaf(nb, c0.z, acc0.z); acc0.w = fmaf(nb, c0.w, acc0.w);
        acc1.x = fmaf(nb, c1.x, acc1.x); acc1.y = fmaf(nb, c1.y, acc1.y);
        acc1.z = fmaf(nb, c1.z, acc1.z); acc1.w = fmaf(nb, c1.w, acc1.w);
    }
    if (j < je) {
        int r = erow[j];
        float nm = enorm[j];
        const float4* hr = H + (size_t)r * D4;
        float4 v0 = hr[q0], v1 = hr[q1];
        acc0.x = fmaf(nm, v0.x, acc0.x); acc0.y = fmaf(nm, v0.y, acc0.y);
        acc0.z = fmaf(nm, v0.z, acc0.z); acc0.w = fmaf(nm, v0.w, acc0.w);
        acc1.x = fmaf(nm, v1.x, acc1.x); acc1.y = fmaf(nm, v1.y, acc1.y);
        acc1.z = fmaf(nm, v1.z, acc1.z); acc1.w = fmaf(nm, v1.w, acc1.w);
    }
    if (outF) {
        float4* op = outF + (size_t)node * D4;
        op[q0] = acc0;
        op[q1] = acc1;
    }
    if (oxh) {
        B4 s0 = split4(acc0), s1 = split4(acc1);
        uint2* ph = oxh + (size_t)node * D4;
        uint2* pl = oxl + (size_t)node * D4;
        ph[q0] = s0.hi; ph[q1] = s1.hi;
        pl[q0] = s0.lo; pl[q1] = s1.lo;
    }
}

// ---------------- launch ----------------
extern "C" void kernel_launch(void* const* d_in, const int* in_sizes, int n_in,
                              void* d_out, int out_size) {
    const int*   ids_all = (const int*)d_in[0];
    const int*   ei_all  = (const int*)d_in[1];
    const float* w_all   = (const float*)d_in[2];
    const float* emb     = (const float*)d_in[3];
    const float* Ws[3] = {(const float*)d_in[4], (const float*)d_in[6], (const float*)d_in[8]};
    const float* bs[3] = {(const float*)d_in[5], (const float*)d_in[7], (const float*)d_in[9]};
    float* out = (float*)d_out;

    void *ph, *pxh, *pxl, *pwh, *pwl, *pd, *pc, *pu, *pp, *pe, *pm, *pbs, *pbo;
    cudaGetSymbolAddress(&ph,  g_h);
    cudaGetSymbolAddress(&pxh, g_xh);
    cudaGetSymbolAddress(&pxl, g_xl);
    cudaGetSymbolAddress(&pwh, g_wh);
    cudaGetSymbolAddress(&pwl, g_wl);
    cudaGetSymbolAddress(&pd,  g_dinv);
    cudaGetSymbolAddress(&pc,  g_cnt);
    cudaGetSymbolAddress(&pu,  g_cur);
    cudaGetSymbolAddress(&pp,  g_ptr);
    cudaGetSymbolAddress(&pe,  g_erow);
    cudaGetSymbolAddress(&pm,  g_enorm);
    cudaGetSymbolAddress(&pbs, g_bsum);
    cudaGetSymbolAddress(&pbo, g_boff);
    float* Hh = (float*)ph;
    __nv_bfloat16* xh = (__nv_bfloat16*)pxh;
    __nv_bfloat16* xl = (__nv_bfloat16*)pxl;
    __nv_bfloat16* wh = (__nv_bfloat16*)pwh;
    __nv_bfloat16* wl = (__nv_bfloat16*)pwl;
    float* dinv = (float*)pd;
    int* cnt = (int*)pc;
    int* cur = (int*)pu;
    int* ptr = (int*)pp;
    int* erow = (int*)pe;
    float* enrm = (float*)pm;
    int* bsum = (int*)pbs;
    int* boff = (int*)pbo;

    const int TPB = 256;
    static int smem_set = 0;
    if (!smem_set) {
        cudaFuncSetAttribute(k_gemm_mma, cudaFuncAttributeMaxDynamicSharedMemorySize,
                             GEMM_SMEM);
        smem_set = 1;
    }

    for (int l = 0; l < 3; l++)
        k_wprep<<<(Dd * Dd + TPB - 1) / TPB, TPB>>>(Ws[l], wh + (size_t)l * Dd * Dd,
                                                    wl + (size_t)l * Dd * Dd);

    // batched prep across all timesteps
    k_init<<<(NT + TPB - 1) / TPB, TPB>>>(dinv, cnt);
    k_edge_prep<<<(ET + TPB - 1) / TPB, TPB>>>(ei_all, w_all, dinv, cnt);
    k_finalize_dinv<<<(NT + TPB - 1) / TPB, TPB>>>(dinv);
    k_scan1<<<SCAN_BLK, 1024>>>(cnt, ptr, cur, bsum);
    k_scan2<<<1, 32>>>(bsum, boff, ptr);
    k_scan3<<<SCAN_BLK, 1024>>>(boff, ptr, cur);
    k_permute<<<(ET + TPB - 1) / TPB, TPB>>>(ei_all, w_all, dinv, cur, erow, enrm);
    k_gather<<<(NT * D4 + TPB - 1) / TPB, TPB>>>(ids_all, (const float4*)emb,
                                                 (uint2*)xh, (uint2*)xl);

    int aggBlocks = (Nn * 32 + TPB - 1) / TPB;
    dim3 ggrid((Nn + 127) / 128, Dd / 128);

    for (int t = 0; t < Tt; t++) {
        size_t xoff = (size_t)t * Nn * Dd;
        float* outT = out + xoff;

        for (int l = 0; l < 3; l++) {
            k_gemm_mma<<<ggrid, 256, GEMM_SMEM>>>(xh + xoff, xl + xoff,
                                                  wh + (size_t)l * Dd * Dd,
                                                  wl + (size_t)l * Dd * Dd, Hh);
            bool last = (l == 2);
            k_aggregate<<<aggBlocks, TPB>>>(ptr + (size_t)t * Nn, erow, enrm,
                                            (const float4*)Hh, dinv + (size_t)t * Nn,
                                            (const float4*)bs[l],
                                            last ? (float4*)outT : (float4*)nullptr,
                                            last ? (uint2*)nullptr : (uint2*)(xh + xoff),
                                            last ? (uint2*)nullptr : (uint2*)(xl + xoff));
        }
    }
}

// round 6
// speedup vs baseline: 2.8871x; 1.1530x over previous
#include <cuda_runtime.h>
#include <cuda_bf16.h>
#include <cuda_fp16.h>
#include <cstdint>

#define Tt 4
#define Nn 50000
#define Ee 800000
#define Dd 256
#define D4 64
#define NT (Tt * Nn)        // 200000
#define ET (Tt * Ee)        // 3200000
#define SCAN_BLK 49         // ceil(200000/4096)

// ---------------- scratch ----------------
__device__ __half         g_h[(size_t)Nn * Dd];          // GEMM output (fp16)
__device__ __nv_bfloat16  g_xh[(size_t)NT * Dd];
__device__ __nv_bfloat16  g_xl[(size_t)NT * Dd];
__device__ __nv_bfloat16  g_wh[3][Dd * Dd];
__device__ __nv_bfloat16  g_wl[3][Dd * Dd];
__device__ float g_dinv[NT];
__device__ int   g_cnt[NT];
__device__ int   g_cur[NT];
__device__ int   g_ptr[NT + 1];
__device__ int   g_bsum[64];
__device__ int   g_boff[64];
__device__ int   g_erow[ET];
__device__ float g_enorm[ET];

// ---------------- helpers ----------------
__device__ __forceinline__ uint32_t pack2(float a, float b) {
    __nv_bfloat162 t;
    t.x = __float2bfloat16_rn(a);
    t.y = __float2bfloat16_rn(b);
    return *reinterpret_cast<uint32_t*>(&t);
}
struct B4 { uint2 hi, lo; };
__device__ __forceinline__ B4 split4(float4 v) {
    __nv_bfloat16 ha = __float2bfloat16_rn(v.x), hb = __float2bfloat16_rn(v.y);
    __nv_bfloat16 hc = __float2bfloat16_rn(v.z), hd = __float2bfloat16_rn(v.w);
    float ra = v.x - __bfloat162float(ha), rb = v.y - __bfloat162float(hb);
    float rc = v.z - __bfloat162float(hc), rd = v.w - __bfloat162float(hd);
    B4 o;
    __nv_bfloat162 t0; t0.x = ha; t0.y = hb;
    __nv_bfloat162 t1; t1.x = hc; t1.y = hd;
    o.hi.x = *reinterpret_cast<uint32_t*>(&t0);
    o.hi.y = *reinterpret_cast<uint32_t*>(&t1);
    o.lo.x = pack2(ra, rb);
    o.lo.y = pack2(rc, rd);
    return o;
}
// unpack uint4 (8 halves) to 8 floats
__device__ __forceinline__ void h8f(uint4 v, float* f) {
    float2 p;
    p = __half22float2(*reinterpret_cast<__half2*>(&v.x)); f[0] = p.x; f[1] = p.y;
    p = __half22float2(*reinterpret_cast<__half2*>(&v.y)); f[2] = p.x; f[3] = p.y;
    p = __half22float2(*reinterpret_cast<__half2*>(&v.z)); f[4] = p.x; f[5] = p.y;
    p = __half22float2(*reinterpret_cast<__half2*>(&v.w)); f[6] = p.x; f[7] = p.y;
}

// ---------------- batched prep (block-diagonal 4-timestep graph) ----------------
__global__ void k_init(float* __restrict__ deg, int* __restrict__ cnt) {
    int i = blockIdx.x * blockDim.x + threadIdx.x;
    if (i < NT) { deg[i] = 1.0f; cnt[i] = 0; }
}

__global__ void k_edge_prep(const int* __restrict__ ei_all, const float* __restrict__ w_all,
                            float* __restrict__ deg, int* __restrict__ cnt) {
    int ge = blockIdx.x * blockDim.x + threadIdx.x;
    if (ge < ET) {
        int t = ge / Ee, e = ge - t * Ee;
        int c = ei_all[(size_t)t * 2 * Ee + Ee + e];
        int gc = t * Nn + c;
        atomicAdd(&deg[gc], w_all[ge]);
        atomicAdd(&cnt[gc], 1);
    }
}

__global__ void k_finalize_dinv(float* __restrict__ deg) {
    int i = blockIdx.x * blockDim.x + threadIdx.x;
    if (i < NT) {
        float d = deg[i];
        deg[i] = (d > 0.0f) ? rsqrtf(d) : 0.0f;
    }
}

__global__ void __launch_bounds__(1024)
k_scan1(const int* __restrict__ cnt, int* __restrict__ ptr, int* __restrict__ cur,
        int* __restrict__ bsum) {
    __shared__ int wt[32];
    int tid = threadIdx.x, lane = tid & 31, wid = tid >> 5;
    int i0 = blockIdx.x * 4096 + tid * 4;
    int4 v = make_int4(0, 0, 0, 0);
    if (i0 + 3 < NT) v = *(const int4*)(cnt + i0);
    else {
        if (i0 < NT)     v.x = cnt[i0];
        if (i0 + 1 < NT) v.y = cnt[i0 + 1];
        if (i0 + 2 < NT) v.z = cnt[i0 + 2];
    }
    int tsum = v.x + v.y + v.z + v.w;
    int s = tsum;
#pragma unroll
    for (int off = 1; off < 32; off <<= 1) {
        int t = __shfl_up_sync(0xffffffffu, s, off);
        if (lane >= off) s += t;
    }
    if (lane == 31) wt[wid] = s;
    __syncthreads();
    if (wid == 0) {
        int ws = wt[lane];
#pragma unroll
        for (int off = 1; off < 32; off <<= 1) {
            int t = __shfl_up_sync(0xffffffffu, ws, off);
            if (lane >= off) ws += t;
        }
        wt[lane] = ws;
    }
    __syncthreads();
    int excl = s - tsum + (wid > 0 ? wt[wid - 1] : 0);
    int p = excl;
    if (i0 < NT)     { cur[i0] = p;     ptr[i0 + 1] = p + v.x; } p += v.x;
    if (i0 + 1 < NT) { cur[i0 + 1] = p; ptr[i0 + 2] = p + v.y; } p += v.y;
    if (i0 + 2 < NT) { cur[i0 + 2] = p; ptr[i0 + 3] = p + v.z; } p += v.z;
    if (i0 + 3 < NT) { cur[i0 + 3] = p; ptr[i0 + 4] = p + v.w; }
    if (tid == 1023) bsum[blockIdx.x] = excl + tsum;
}

__global__ void k_scan2(const int* __restrict__ bsum, int* __restrict__ boff,
                        int* __restrict__ ptr) {
    if (threadIdx.x == 0) {
        ptr[0] = 0;
        int run = 0;
        for (int b = 0; b < SCAN_BLK; b++) { boff[b] = run; run += bsum[b]; }
    }
}

__global__ void __launch_bounds__(1024)
k_scan3(const int* __restrict__ boff, int* __restrict__ ptr, int* __restrict__ cur) {
    int off = boff[blockIdx.x];
    int i0 = blockIdx.x * 4096 + threadIdx.x * 4;
#pragma unroll
    for (int k = 0; k < 4; k++) {
        int i = i0 + k;
        if (i < NT) { cur[i] += off; ptr[i + 1] += off; }
    }
}

__global__ void k_permute(const int* __restrict__ ei_all, const float* __restrict__ w_all,
                          const float* __restrict__ dinv, int* __restrict__ cur,
                          int* __restrict__ erow, float* __restrict__ enorm) {
    int ge = blockIdx.x * blockDim.x + threadIdx.x;
    if (ge < ET) {
        int t = ge / Ee, e = ge - t * Ee;
        const int* base = ei_all + (size_t)t * 2 * Ee;
        int r = base[e], c = base[Ee + e];
        int gr = t * Nn + r, gc = t * Nn + c;
        float nm = dinv[gr] * w_all[ge] * dinv[gc];
        int pos = atomicAdd(&cur[gc], 1);
        erow[pos] = r;
        enorm[pos] = nm;
    }
}

__global__ void k_wprep(const float* __restrict__ W, __nv_bfloat16* __restrict__ wh,
                        __nv_bfloat16* __restrict__ wl) {
    int idx = blockIdx.x * blockDim.x + threadIdx.x;
    if (idx < Dd * Dd) {
        int n = idx >> 8, k = idx & 255;
        float w = W[k * Dd + n];
        __nv_bfloat16 h = __float2bfloat16_rn(w);
        wh[idx] = h;
        wl[idx] = __float2bfloat16_rn(w - __bfloat162float(h));
    }
}

__global__ void k_gather(const int* __restrict__ ids, const float4* __restrict__ emb,
                         uint2* __restrict__ xh, uint2* __restrict__ xl) {
    int idx = blockIdx.x * blockDim.x + threadIdx.x;
    if (idx < NT * D4) {
        int i = idx >> 6, q = idx & 63;
        float4 v = emb[(size_t)ids[i] * D4 + q];
        B4 s = split4(v);
        xh[idx] = s.hi;
        xl[idx] = s.lo;
    }
}

// ---------------- mma.sync bf16 GEMM (H output fp16) ----------------
__device__ __forceinline__ uint32_t swz(int row, int c) {
    return (uint32_t)(row * 64 + ((c ^ ((row >> 1) & 3)) << 4));
}

#define GEMM_SMEM 65536

__global__ void __launch_bounds__(256)
k_gemm_mma(const __nv_bfloat16* __restrict__ xh, const __nv_bfloat16* __restrict__ xl,
           const __nv_bfloat16* __restrict__ wh, const __nv_bfloat16* __restrict__ wl,
           __half* __restrict__ H) {
    extern __shared__ __align__(128) char sm[];

    const int tid = threadIdx.x;
    const int wid = tid >> 5, lane = tid & 31;
    const int m0 = blockIdx.x * 128, n0 = blockIdx.y * 128;
    const int mw = wid >> 2, nw = wid & 3;

    float acc[4][4][4] = {};

    auto issue = [&](int kc, int stage) {
        char* sbase = sm + stage * 32768;
#pragma unroll
        for (int i = 0; i < 8; i++) {
            int u = tid + i * 256;
            int tile = u >> 9, idx = u & 511;
            int row = idx >> 2, c = idx & 3;
            uint32_t dst = (uint32_t)__cvta_generic_to_shared(
                sbase + tile * 8192 + swz(row, c));
            if (tile < 2) {
                const __nv_bfloat16* A = (tile == 0) ? xh : xl;
                int gm = m0 + row;
                int ok = (gm < Nn);
                const void* src = A + (size_t)(ok ? gm : 0) * Dd + kc * 32 + c * 8;
                int sz = ok ? 16 : 0;
                asm volatile("cp.async.ca.shared.global [%0], [%1], 16, %2;"
                             :: "r"(dst), "l"(src), "r"(sz));
            } else {
                const __nv_bfloat16* B = (tile == 2) ? wh : wl;
                const void* src = B + (size_t)(n0 + row) * Dd + kc * 32 + c * 8;
                asm volatile("cp.async.ca.shared.global [%0], [%1], 16;"
                             :: "r"(dst), "l"(src));
            }
        }
        asm volatile("cp.async.commit_group;");
    };

    issue(0, 0);
    for (int it = 0; it < 8; it++) {
        int buf = it & 1;
        if (it + 1 < 8) {
            issue(it + 1, buf ^ 1);
            asm volatile("cp.async.wait_group 1;");
        } else {
            asm volatile("cp.async.wait_group 0;");
        }
        __syncthreads();
        char* pAh = sm + buf * 32768;
        char* pAl = pAh + 8192;
        char* pBh = pAh + 16384;
        char* pBl = pAh + 24576;

#pragma unroll
        for (int ks = 0; ks < 2; ks++) {
            int arow_c = ks * 2 + ((lane >> 4) & 1);
            int brow = ((lane & 7) + ((lane & 16) ? 8 : 0));
            int bc = ks * 2 + ((lane & 8) ? 1 : 0);
            uint32_t afh[4][4], afl[4][4];
#pragma unroll
            for (int mt = 0; mt < 4; mt++) {
                int row = mw * 64 + mt * 16 + (lane & 15);
                uint32_t ah = (uint32_t)__cvta_generic_to_shared(pAh + swz(row, arow_c));
                uint32_t al = (uint32_t)__cvta_generic_to_shared(pAl + swz(row, arow_c));
                asm volatile("ldmatrix.sync.aligned.m8n8.x4.shared.b16 {%0,%1,%2,%3}, [%4];"
                             : "=r"(afh[mt][0]), "=r"(afh[mt][1]),
                               "=r"(afh[mt][2]), "=r"(afh[mt][3]) : "r"(ah));
                asm volatile("ldmatrix.sync.aligned.m8n8.x4.shared.b16 {%0,%1,%2,%3}, [%4];"
                             : "=r"(afl[mt][0]), "=r"(afl[mt][1]),
                               "=r"(afl[mt][2]), "=r"(afl[mt][3]) : "r"(al));
            }
            uint32_t bfh[4][2], bfl[4][2];
#pragma unroll
            for (int ntp = 0; ntp < 2; ntp++) {
                int row = nw * 32 + ntp * 16 + brow;
                uint32_t bh = (uint32_t)__cvta_generic_to_shared(pBh + swz(row, bc));
                uint32_t bl = (uint32_t)__cvta_generic_to_shared(pBl + swz(row, bc));
                uint32_t r0, r1, r2, r3;
                asm volatile("ldmatrix.sync.aligned.m8n8.x4.shared.b16 {%0,%1,%2,%3}, [%4];"
                             : "=r"(r0), "=r"(r1), "=r"(r2), "=r"(r3) : "r"(bh));
                bfh[ntp * 2][0] = r0; bfh[ntp * 2][1] = r1;
                bfh[ntp * 2 + 1][0] = r2; bfh[ntp * 2 + 1][1] = r3;
                asm volatile("ldmatrix.sync.aligned.m8n8.x4.shared.b16 {%0,%1,%2,%3}, [%4];"
                             : "=r"(r0), "=r"(r1), "=r"(r2), "=r"(r3) : "r"(bl));
                bfl[ntp * 2][0] = r0; bfl[ntp * 2][1] = r1;
                bfl[ntp * 2 + 1][0] = r2; bfl[ntp * 2 + 1][1] = r3;
            }
#define MMA(af, bf) \
    asm volatile("mma.sync.aligned.m16n8k16.row.col.f32.bf16.bf16.f32 " \
                 "{%0,%1,%2,%3}, {%4,%5,%6,%7}, {%8,%9}, {%0,%1,%2,%3};" \
                 : "+f"(acc[mt][nt][0]), "+f"(acc[mt][nt][1]), \
                   "+f"(acc[mt][nt][2]), "+f"(acc[mt][nt][3]) \
                 : "r"(af[mt][0]), "r"(af[mt][1]), "r"(af[mt][2]), "r"(af[mt][3]), \
                   "r"(bf[nt][0]), "r"(bf[nt][1]))
#pragma unroll
            for (int mt = 0; mt < 4; mt++)
#pragma unroll
                for (int nt = 0; nt < 4; nt++) {
                    MMA(afh, bfh);
                    MMA(afh, bfl);
                    MMA(afl, bfh);
                }
#undef MMA
        }
        __syncthreads();
    }

#pragma unroll
    for (int mt = 0; mt < 4; mt++) {
        int mm = m0 + mw * 64 + mt * 16 + (lane >> 2);
#pragma unroll
        for (int nt = 0; nt < 4; nt++) {
            int cc = n0 + nw * 32 + nt * 8 + 2 * (lane & 3);
            if (mm < Nn) {
                __half2 h01 = __floats2half2_rn(acc[mt][nt][0], acc[mt][nt][1]);
                *(uint32_t*)(H + (size_t)mm * Dd + cc) = *reinterpret_cast<uint32_t*>(&h01);
            }
            if (mm + 8 < Nn) {
                __half2 h23 = __floats2half2_rn(acc[mt][nt][2], acc[mt][nt][3]);
                *(uint32_t*)(H + (size_t)(mm + 8) * Dd + cc) = *reinterpret_cast<uint32_t*>(&h23);
            }
        }
    }
}

// ---------------- aggregate: warp/node, fp16 H rows (1 uint4 per lane per edge) ----
__global__ void __launch_bounds__(256)
k_aggregate(const int* __restrict__ ptr, const int* __restrict__ erow,
            const float* __restrict__ enorm, const uint4* __restrict__ H,
            const float* __restrict__ dinv, const float4* __restrict__ bias,
            float4* __restrict__ outF, uint4* __restrict__ oxh, uint4* __restrict__ oxl) {
    int warp = (blockIdx.x * blockDim.x + threadIdx.x) >> 5;
    int lane = threadIdx.x & 31;
    if (warp >= Nn) return;
    int node = warp;
    // H row = 256 halves = 32 uint4; lane handles chunk `lane` (8 halves)

    float s = dinv[node];
    s = s * s;
    float f[8], acc[8];
    h8f(H[(size_t)node * 32 + lane], f);
    float4 b0 = bias[lane * 2], b1 = bias[lane * 2 + 1];
    acc[0] = fmaf(s, f[0], b0.x); acc[1] = fmaf(s, f[1], b0.y);
    acc[2] = fmaf(s, f[2], b0.z); acc[3] = fmaf(s, f[3], b0.w);
    acc[4] = fmaf(s, f[4], b1.x); acc[5] = fmaf(s, f[5], b1.y);
    acc[6] = fmaf(s, f[6], b1.z); acc[7] = fmaf(s, f[7], b1.w);

    int jb = ptr[node], je = ptr[node + 1];
    int j = jb;
    for (; j + 1 < je; j += 2) {
        int ra = erow[j], rb = erow[j + 1];
        float na = enorm[j], nb = enorm[j + 1];
        uint4 va = H[(size_t)ra * 32 + lane];
        uint4 vb = H[(size_t)rb * 32 + lane];
        float fa[8], fb[8];
        h8f(va, fa); h8f(vb, fb);
#pragma unroll
        for (int i = 0; i < 8; i++) acc[i] = fmaf(na, fa[i], acc[i]);
#pragma unroll
        for (int i = 0; i < 8; i++) acc[i] = fmaf(nb, fb[i], acc[i]);
    }
    if (j < je) {
        int r = erow[j];
        float nm = enorm[j];
        float fr[8];
        h8f(H[(size_t)r * 32 + lane], fr);
#pragma unroll
        for (int i = 0; i < 8; i++) acc[i] = fmaf(nm, fr[i], acc[i]);
    }

    float4 a0 = make_float4(acc[0], acc[1], acc[2], acc[3]);
    float4 a1 = make_float4(acc[4], acc[5], acc[6], acc[7]);
    if (outF) {
        float4* op = outF + (size_t)node * D4 + lane * 2;
        op[0] = a0;
        op[1] = a1;
    }
    if (oxh) {
        B4 s0 = split4(a0), s1 = split4(a1);
        uint4 hi = make_uint4(s0.hi.x, s0.hi.y, s1.hi.x, s1.hi.y);
        uint4 lo = make_uint4(s0.lo.x, s0.lo.y, s1.lo.x, s1.lo.y);
        oxh[(size_t)node * 32 + lane] = hi;
        oxl[(size_t)node * 32 + lane] = lo;
    }
}

// ---------------- launch ----------------
extern "C" void kernel_launch(void* const* d_in, const int* in_sizes, int n_in,
                              void* d_out, int out_size) {
    const int*   ids_all = (const int*)d_in[0];
    const int*   ei_all  = (const int*)d_in[1];
    const float* w_all   = (const float*)d_in[2];
    const float* emb     = (const float*)d_in[3];
    const float* Ws[3] = {(const float*)d_in[4], (const float*)d_in[6], (const float*)d_in[8]};
    const float* bs[3] = {(const float*)d_in[5], (const float*)d_in[7], (const float*)d_in[9]};
    float* out = (float*)d_out;

    void *ph, *pxh, *pxl, *pwh, *pwl, *pd, *pc, *pu, *pp, *pe, *pm, *pbs, *pbo;
    cudaGetSymbolAddress(&ph,  g_h);
    cudaGetSymbolAddress(&pxh, g_xh);
    cudaGetSymbolAddress(&pxl, g_xl);
    cudaGetSymbolAddress(&pwh, g_wh);
    cudaGetSymbolAddress(&pwl, g_wl);
    cudaGetSymbolAddress(&pd,  g_dinv);
    cudaGetSymbolAddress(&pc,  g_cnt);
    cudaGetSymbolAddress(&pu,  g_cur);
    cudaGetSymbolAddress(&pp,  g_ptr);
    cudaGetSymbolAddress(&pe,  g_erow);
    cudaGetSymbolAddress(&pm,  g_enorm);
    cudaGetSymbolAddress(&pbs, g_bsum);
    cudaGetSymbolAddress(&pbo, g_boff);
    __half* Hh = (__half*)ph;
    __nv_bfloat16* xh = (__nv_bfloat16*)pxh;
    __nv_bfloat16* xl = (__nv_bfloat16*)pxl;
    __nv_bfloat16* wh = (__nv_bfloat16*)pwh;
    __nv_bfloat16* wl = (__nv_bfloat16*)pwl;
    float* dinv = (float*)pd;
    int* cnt = (int*)pc;
    int* cur = (int*)pu;
    int* ptr = (int*)pp;
    int* erow = (int*)pe;
    float* enrm = (float*)pm;
    int* bsum = (int*)pbs;
    int* boff = (int*)pbo;

    const int TPB = 256;
    static int smem_set = 0;
    if (!smem_set) {
        cudaFuncSetAttribute(k_gemm_mma, cudaFuncAttributeMaxDynamicSharedMemorySize,
                             GEMM_SMEM);
        smem_set = 1;
    }

    for (int l = 0; l < 3; l++)
        k_wprep<<<(Dd * Dd + TPB - 1) / TPB, TPB>>>(Ws[l], wh + (size_t)l * Dd * Dd,
                                                    wl + (size_t)l * Dd * Dd);

    k_init<<<(NT + TPB - 1) / TPB, TPB>>>(dinv, cnt);
    k_edge_prep<<<(ET + TPB - 1) / TPB, TPB>>>(ei_all, w_all, dinv, cnt);
    k_finalize_dinv<<<(NT + TPB - 1) / TPB, TPB>>>(dinv);
    k_scan1<<<SCAN_BLK, 1024>>>(cnt, ptr, cur, bsum);
    k_scan2<<<1, 32>>>(bsum, boff, ptr);
    k_scan3<<<SCAN_BLK, 1024>>>(boff, ptr, cur);
    k_permute<<<(ET + TPB - 1) / TPB, TPB>>>(ei_all, w_all, dinv, cur, erow, enrm);
    k_gather<<<(NT * D4 + TPB - 1) / TPB, TPB>>>(ids_all, (const float4*)emb,
                                                 (uint2*)xh, (uint2*)xl);

    int aggBlocks = (Nn * 32 + TPB - 1) / TPB;
    dim3 ggrid((Nn + 127) / 128, Dd / 128);

    for (int t = 0; t < Tt; t++) {
        size_t xoff = (size_t)t * Nn * Dd;
        float* outT = out + xoff;

        for (int l = 0; l < 3; l++) {
            k_gemm_mma<<<ggrid, 256, GEMM_SMEM>>>(xh + xoff, xl + xoff,
                                                  wh + (size_t)l * Dd * Dd,
                                                  wl + (size_t)l * Dd * Dd, Hh);
            bool last = (l == 2);
            k_aggregate<<<aggBlocks, TPB>>>(ptr + (size_t)t * Nn, erow, enrm,
                                            (const uint4*)Hh, dinv + (size_t)t * Nn,
                                            (const float4*)bs[l],
                                            last ? (float4*)outT : (float4*)nullptr,
                                            last ? (uint4*)nullptr : (uint4*)(xh + xoff),
                                            last ? (uint4*)nullptr : (uint4*)(xl + xoff));
        }
    }
}

// round 7
// speedup vs baseline: 4.3894x; 1.5203x over previous
#include <cuda_runtime.h>
#include <cuda_fp16.h>
#include <cstdint>

#define Tt 4
#define Nn 50000
#define Ee 800000
#define Dd 256
#define D4 64
#define NT (Tt * Nn)        // 200000
#define ET (Tt * Ee)        // 3200000
#define SCAN_BLK 49         // ceil(200000/4096)

// ---------------- scratch ----------------
__device__ __half g_h0[(size_t)Nn * Dd];     // H buffer (even t)
__device__ __half g_h1[(size_t)Nn * Dd];     // H buffer (odd t)
__device__ __half g_x[(size_t)NT * Dd];      // X (fp16)
__device__ __half g_w[3][Dd * Dd];           // W^T (fp16) [N,K]
__device__ float g_dinv[NT];
__device__ int   g_cnt[NT];
__device__ int   g_cur[NT];
__device__ int   g_ptr[NT + 1];
__device__ int   g_bsum[64];
__device__ int   g_boff[64];
__device__ int   g_erow[ET];
__device__ float g_enorm[ET];

// ---------------- helpers ----------------
__device__ __forceinline__ void h8f(uint4 v, float* f) {
    float2 p;
    p = __half22float2(*reinterpret_cast<__half2*>(&v.x)); f[0] = p.x; f[1] = p.y;
    p = __half22float2(*reinterpret_cast<__half2*>(&v.y)); f[2] = p.x; f[3] = p.y;
    p = __half22float2(*reinterpret_cast<__half2*>(&v.z)); f[4] = p.x; f[5] = p.y;
    p = __half22float2(*reinterpret_cast<__half2*>(&v.w)); f[6] = p.x; f[7] = p.y;
}
__device__ __forceinline__ uint32_t f2h2(float a, float b) {
    __half2 t = __floats2half2_rn(a, b);
    return *reinterpret_cast<uint32_t*>(&t);
}

// ---------------- batched prep ----------------
__global__ void k_init(float* __restrict__ deg, int* __restrict__ cnt) {
    int i = blockIdx.x * blockDim.x + threadIdx.x;
    if (i < NT) { deg[i] = 1.0f; cnt[i] = 0; }
}

__global__ void k_edge_prep(const int* __restrict__ ei_all, const float* __restrict__ w_all,
                            float* __restrict__ deg, int* __restrict__ cnt) {
    int ge = blockIdx.x * blockDim.x + threadIdx.x;
    if (ge < ET) {
        int t = ge / Ee, e = ge - t * Ee;
        int c = ei_all[(size_t)t * 2 * Ee + Ee + e];
        int gc = t * Nn + c;
        atomicAdd(&deg[gc], w_all[ge]);
        atomicAdd(&cnt[gc], 1);
    }
}

__global__ void k_finalize_dinv(float* __restrict__ deg) {
    int i = blockIdx.x * blockDim.x + threadIdx.x;
    if (i < NT) {
        float d = deg[i];
        deg[i] = (d > 0.0f) ? rsqrtf(d) : 0.0f;
    }
}

__global__ void __launch_bounds__(1024)
k_scan1(const int* __restrict__ cnt, int* __restrict__ ptr, int* __restrict__ cur,
        int* __restrict__ bsum) {
    __shared__ int wt[32];
    int tid = threadIdx.x, lane = tid & 31, wid = tid >> 5;
    int i0 = blockIdx.x * 4096 + tid * 4;
    int4 v = make_int4(0, 0, 0, 0);
    if (i0 + 3 < NT) v = *(const int4*)(cnt + i0);
    else {
        if (i0 < NT)     v.x = cnt[i0];
        if (i0 + 1 < NT) v.y = cnt[i0 + 1];
        if (i0 + 2 < NT) v.z = cnt[i0 + 2];
    }
    int tsum = v.x + v.y + v.z + v.w;
    int s = tsum;
#pragma unroll
    for (int off = 1; off < 32; off <<= 1) {
        int t = __shfl_up_sync(0xffffffffu, s, off);
        if (lane >= off) s += t;
    }
    if (lane == 31) wt[wid] = s;
    __syncthreads();
    if (wid == 0) {
        int ws = wt[lane];
#pragma unroll
        for (int off = 1; off < 32; off <<= 1) {
            int t = __shfl_up_sync(0xffffffffu, ws, off);
            if (lane >= off) ws += t;
        }
        wt[lane] = ws;
    }
    __syncthreads();
    int excl = s - tsum + (wid > 0 ? wt[wid - 1] : 0);
    int p = excl;
    if (i0 < NT)     { cur[i0] = p;     ptr[i0 + 1] = p + v.x; } p += v.x;
    if (i0 + 1 < NT) { cur[i0 + 1] = p; ptr[i0 + 2] = p + v.y; } p += v.y;
    if (i0 + 2 < NT) { cur[i0 + 2] = p; ptr[i0 + 3] = p + v.z; } p += v.z;
    if (i0 + 3 < NT) { cur[i0 + 3] = p; ptr[i0 + 4] = p + v.w; }
    if (tid == 1023) bsum[blockIdx.x] = excl + tsum;
}

__global__ void k_scan2(const int* __restrict__ bsum, int* __restrict__ boff,
                        int* __restrict__ ptr) {
    if (threadIdx.x == 0) {
        ptr[0] = 0;
        int run = 0;
        for (int b = 0; b < SCAN_BLK; b++) { boff[b] = run; run += bsum[b]; }
    }
}

__global__ void __launch_bounds__(1024)
k_scan3(const int* __restrict__ boff, int* __restrict__ ptr, int* __restrict__ cur) {
    int off = boff[blockIdx.x];
    int i0 = blockIdx.x * 4096 + threadIdx.x * 4;
#pragma unroll
    for (int k = 0; k < 4; k++) {
        int i = i0 + k;
        if (i < NT) { cur[i] += off; ptr[i + 1] += off; }
    }
}

__global__ void k_permute(const int* __restrict__ ei_all, const float* __restrict__ w_all,
                          const float* __restrict__ dinv, int* __restrict__ cur,
                          int* __restrict__ erow, float* __restrict__ enorm) {
    int ge = blockIdx.x * blockDim.x + threadIdx.x;
    if (ge < ET) {
        int t = ge / Ee, e = ge - t * Ee;
        const int* base = ei_all + (size_t)t * 2 * Ee;
        int r = base[e], c = base[Ee + e];
        int gr = t * Nn + r, gc = t * Nn + c;
        float nm = dinv[gr] * w_all[ge] * dinv[gc];
        int pos = atomicAdd(&cur[gc], 1);
        erow[pos] = r;
        enorm[pos] = nm;
    }
}

// W^T fp16: w[n*256+k] = fp16(W[k*256+n])
__global__ void k_wprep(const float* __restrict__ W, __half* __restrict__ wt) {
    int idx = blockIdx.x * blockDim.x + threadIdx.x;
    if (idx < Dd * Dd) {
        int n = idx >> 8, k = idx & 255;
        wt[idx] = __float2half_rn(W[k * Dd + n]);
    }
}

// embedding gather -> fp16 x (4 floats / thread)
__global__ void k_gather(const int* __restrict__ ids, const float4* __restrict__ emb,
                         uint2* __restrict__ x) {
    int idx = blockIdx.x * blockDim.x + threadIdx.x;
    if (idx < NT * 64) {
        int i = idx >> 6, q = idx & 63;
        float4 v = emb[(size_t)ids[i] * 64 + q];
        x[idx] = make_uint2(f2h2(v.x, v.y), f2h2(v.z, v.w));
    }
}

// ---------------- mma.sync fp16 GEMM: H[Nn,256] = X @ W ----------------
// CTA tile 128x128x32, 2-stage cp.async pipeline, fp32 accum, fp16 out.
__device__ __forceinline__ uint32_t swz(int row, int c) {
    return (uint32_t)(row * 64 + ((c ^ ((row >> 1) & 3)) << 4));
}

#define GEMM_SMEM 32768   // 2 stages x (A 8KB + B 8KB)

__global__ void __launch_bounds__(256)
k_gemm_mma(const __half* __restrict__ x, const __half* __restrict__ wt,
           __half* __restrict__ H) {
    extern __shared__ __align__(128) char sm[];

    const int tid = threadIdx.x;
    const int wid = tid >> 5, lane = tid & 31;
    const int m0 = blockIdx.x * 128, n0 = blockIdx.y * 128;
    const int mw = wid >> 2, nw = wid & 3;

    float acc[4][4][4] = {};

    auto issue = [&](int kc, int stage) {
        char* sbase = sm + stage * 16384;
#pragma unroll
        for (int i = 0; i < 4; i++) {
            int u = tid + i * 256;
            int tile = u >> 9, idx = u & 511;
            int row = idx >> 2, c = idx & 3;
            uint32_t dst = (uint32_t)__cvta_generic_to_shared(
                sbase + tile * 8192 + swz(row, c));
            if (tile == 0) {
                int gm = m0 + row;
                int ok = (gm < Nn);
                const void* src = x + (size_t)(ok ? gm : 0) * Dd + kc * 32 + c * 8;
                int sz = ok ? 16 : 0;
                asm volatile("cp.async.ca.shared.global [%0], [%1], 16, %2;"
                             :: "r"(dst), "l"(src), "r"(sz));
            } else {
                const void* src = wt + (size_t)(n0 + row) * Dd + kc * 32 + c * 8;
                asm volatile("cp.async.ca.shared.global [%0], [%1], 16;"
                             :: "r"(dst), "l"(src));
            }
        }
        asm volatile("cp.async.commit_group;");
    };

    issue(0, 0);
    for (int it = 0; it < 8; it++) {
        int buf = it & 1;
        if (it + 1 < 8) {
            issue(it + 1, buf ^ 1);
            asm volatile("cp.async.wait_group 1;");
        } else {
            asm volatile("cp.async.wait_group 0;");
        }
        __syncthreads();
        char* pA = sm + buf * 16384;
        char* pB = pA + 8192;

#pragma unroll
        for (int ks = 0; ks < 2; ks++) {
            int ac = ks * 2 + ((lane >> 4) & 1);
            int brow = (lane & 7) + ((lane & 16) ? 8 : 0);
            int bc = ks * 2 + ((lane & 8) ? 1 : 0);
            uint32_t af[4][4];
#pragma unroll
            for (int mt = 0; mt < 4; mt++) {
                int row = mw * 64 + mt * 16 + (lane & 15);
                uint32_t a = (uint32_t)__cvta_generic_to_shared(pA + swz(row, ac));
                asm volatile("ldmatrix.sync.aligned.m8n8.x4.shared.b16 {%0,%1,%2,%3}, [%4];"
                             : "=r"(af[mt][0]), "=r"(af[mt][1]),
                               "=r"(af[mt][2]), "=r"(af[mt][3]) : "r"(a));
            }
            uint32_t bf[4][2];
#pragma unroll
            for (int ntp = 0; ntp < 2; ntp++) {
                int row = nw * 32 + ntp * 16 + brow;
                uint32_t b = (uint32_t)__cvta_generic_to_shared(pB + swz(row, bc));
                uint32_t r0, r1, r2, r3;
                asm volatile("ldmatrix.sync.aligned.m8n8.x4.shared.b16 {%0,%1,%2,%3}, [%4];"
                             : "=r"(r0), "=r"(r1), "=r"(r2), "=r"(r3) : "r"(b));
                bf[ntp * 2][0] = r0; bf[ntp * 2][1] = r1;
                bf[ntp * 2 + 1][0] = r2; bf[ntp * 2 + 1][1] = r3;
            }
#pragma unroll
            for (int mt = 0; mt < 4; mt++)
#pragma unroll
                for (int nt = 0; nt < 4; nt++) {
                    asm volatile(
                        "mma.sync.aligned.m16n8k16.row.col.f32.f16.f16.f32 "
                        "{%0,%1,%2,%3}, {%4,%5,%6,%7}, {%8,%9}, {%0,%1,%2,%3};"
                        : "+f"(acc[mt][nt][0]), "+f"(acc[mt][nt][1]),
                          "+f"(acc[mt][nt][2]), "+f"(acc[mt][nt][3])
                        : "r"(af[mt][0]), "r"(af[mt][1]), "r"(af[mt][2]), "r"(af[mt][3]),
                          "r"(bf[nt][0]), "r"(bf[nt][1]));
                }
        }
        __syncthreads();
    }

#pragma unroll
    for (int mt = 0; mt < 4; mt++) {
        int mm = m0 + mw * 64 + mt * 16 + (lane >> 2);
#pragma unroll
        for (int nt = 0; nt < 4; nt++) {
            int cc = n0 + nw * 32 + nt * 8 + 2 * (lane & 3);
            if (mm < Nn)
                *(uint32_t*)(H + (size_t)mm * Dd + cc) = f2h2(acc[mt][nt][0], acc[mt][nt][1]);
            if (mm + 8 < Nn)
                *(uint32_t*)(H + (size_t)(mm + 8) * Dd + cc) = f2h2(acc[mt][nt][2], acc[mt][nt][3]);
        }
    }
}

// ---------------- aggregate: warp/node, fp16 H rows ----------------
__global__ void __launch_bounds__(256)
k_aggregate(const int* __restrict__ ptr, const int* __restrict__ erow,
            const float* __restrict__ enorm, const uint4* __restrict__ H,
            const float* __restrict__ dinv, const float4* __restrict__ bias,
            float4* __restrict__ outF, uint4* __restrict__ ox) {
    int warp = (blockIdx.x * blockDim.x + threadIdx.x) >> 5;
    int lane = threadIdx.x & 31;
    if (warp >= Nn) return;
    int node = warp;

    float s = dinv[node];
    s = s * s;
    float f[8], acc[8];
    h8f(H[(size_t)node * 32 + lane], f);
    float4 b0 = bias[lane * 2], b1 = bias[lane * 2 + 1];
    acc[0] = fmaf(s, f[0], b0.x); acc[1] = fmaf(s, f[1], b0.y);
    acc[2] = fmaf(s, f[2], b0.z); acc[3] = fmaf(s, f[3], b0.w);
    acc[4] = fmaf(s, f[4], b1.x); acc[5] = fmaf(s, f[5], b1.y);
    acc[6] = fmaf(s, f[6], b1.z); acc[7] = fmaf(s, f[7], b1.w);

    int jb = ptr[node], je = ptr[node + 1];
    int j = jb;
    for (; j + 1 < je; j += 2) {
        int ra = erow[j], rb = erow[j + 1];
        float na = enorm[j], nb = enorm[j + 1];
        uint4 va = H[(size_t)ra * 32 + lane];
        uint4 vb = H[(size_t)rb * 32 + lane];
        float fa[8], fb[8];
        h8f(va, fa); h8f(vb, fb);
#pragma unroll
        for (int i = 0; i < 8; i++) acc[i] = fmaf(na, fa[i], acc[i]);
#pragma unroll
        for (int i = 0; i < 8; i++) acc[i] = fmaf(nb, fb[i], acc[i]);
    }
    if (j < je) {
        int r = erow[j];
        float nm = enorm[j];
        float fr[8];
        h8f(H[(size_t)r * 32 + lane], fr);
#pragma unroll
        for (int i = 0; i < 8; i++) acc[i] = fmaf(nm, fr[i], acc[i]);
    }

    if (outF) {
        float4* op = outF + (size_t)node * D4 + lane * 2;
        op[0] = make_float4(acc[0], acc[1], acc[2], acc[3]);
        op[1] = make_float4(acc[4], acc[5], acc[6], acc[7]);
    }
    if (ox) {
        ox[(size_t)node * 32 + lane] = make_uint4(f2h2(acc[0], acc[1]), f2h2(acc[2], acc[3]),
                                                  f2h2(acc[4], acc[5]), f2h2(acc[6], acc[7]));
    }
}

// ---------------- launch ----------------
extern "C" void kernel_launch(void* const* d_in, const int* in_sizes, int n_in,
                              void* d_out, int out_size) {
    const int*   ids_all = (const int*)d_in[0];
    const int*   ei_all  = (const int*)d_in[1];
    const float* w_all   = (const float*)d_in[2];
    const float* emb     = (const float*)d_in[3];
    const float* Ws[3] = {(const float*)d_in[4], (const float*)d_in[6], (const float*)d_in[8]};
    const float* bs[3] = {(const float*)d_in[5], (const float*)d_in[7], (const float*)d_in[9]};
    float* out = (float*)d_out;

    void *ph0, *ph1, *px, *pw, *pd, *pc, *pu, *pp, *pe, *pm, *pbs, *pbo;
    cudaGetSymbolAddress(&ph0, g_h0);
    cudaGetSymbolAddress(&ph1, g_h1);
    cudaGetSymbolAddress(&px,  g_x);
    cudaGetSymbolAddress(&pw,  g_w);
    cudaGetSymbolAddress(&pd,  g_dinv);
    cudaGetSymbolAddress(&pc,  g_cnt);
    cudaGetSymbolAddress(&pu,  g_cur);
    cudaGetSymbolAddress(&pp,  g_ptr);
    cudaGetSymbolAddress(&pe,  g_erow);
    cudaGetSymbolAddress(&pm,  g_enorm);
    cudaGetSymbolAddress(&pbs, g_bsum);
    cudaGetSymbolAddress(&pbo, g_boff);
    __half* H[2] = {(__half*)ph0, (__half*)ph1};
    __half* x  = (__half*)px;
    __half* wt = (__half*)pw;
    float* dinv = (float*)pd;
    int* cnt = (int*)pc;
    int* cur = (int*)pu;
    int* ptr = (int*)pp;
    int* erow = (int*)pe;
    float* enrm = (float*)pm;
    int* bsum = (int*)pbs;
    int* boff = (int*)pbo;

    const int TPB = 256;
    static cudaStream_t s2 = nullptr;
    static cudaEvent_t evF = nullptr, evJ = nullptr;
    if (!s2) {
        cudaStreamCreateWithFlags(&s2, cudaStreamNonBlocking);
        cudaEventCreateWithFlags(&evF, cudaEventDisableTiming);
        cudaEventCreateWithFlags(&evJ, cudaEventDisableTiming);
        cudaFuncSetAttribute(k_gemm_mma, cudaFuncAttributeMaxDynamicSharedMemorySize,
                             GEMM_SMEM);
    }

    // prep (capture/default stream)
    for (int l = 0; l < 3; l++)
        k_wprep<<<(Dd * Dd + TPB - 1) / TPB, TPB>>>(Ws[l], wt + (size_t)l * Dd * Dd);
    k_init<<<(NT + TPB - 1) / TPB, TPB>>>(dinv, cnt);
    k_edge_prep<<<(ET + TPB - 1) / TPB, TPB>>>(ei_all, w_all, dinv, cnt);
    k_finalize_dinv<<<(NT + TPB - 1) / TPB, TPB>>>(dinv);
    k_scan1<<<SCAN_BLK, 1024>>>(cnt, ptr, cur, bsum);
    k_scan2<<<1, 32>>>(bsum, boff, ptr);
    k_scan3<<<SCAN_BLK, 1024>>>(boff, ptr, cur);
    k_permute<<<(ET + TPB - 1) / TPB, TPB>>>(ei_all, w_all, dinv, cur, erow, enrm);
    k_gather<<<(NT * 64 + TPB - 1) / TPB, TPB>>>(ids_all, (const float4*)emb, (uint2*)x);

    // fork odd timesteps onto s2
    cudaEventRecord(evF, 0);
    cudaStreamWaitEvent(s2, evF, 0);

    int aggBlocks = (Nn * 32 + TPB - 1) / TPB;
    dim3 ggrid((Nn + 127) / 128, Dd / 128);

    for (int t = 0; t < Tt; t++) {
        cudaStream_t st = (t & 1) ? s2 : (cudaStream_t)0;
        __half* Hh = H[t & 1];
        size_t xoff = (size_t)t * Nn * Dd;
        float* outT = out + xoff;

        for (int l = 0; l < 3; l++) {
            k_gemm_mma<<<ggrid, 256, GEMM_SMEM, st>>>(x + xoff,
                                                      wt + (size_t)l * Dd * Dd, Hh);
            bool last = (l == 2);
            k_aggregate<<<aggBlocks, TPB, 0, st>>>(ptr + (size_t)t * Nn, erow, enrm,
                                                   (const uint4*)Hh, dinv + (size_t)t * Nn,
                                                   (const float4*)bs[l],
                                                   last ? (float4*)outT : (float4*)nullptr,
                                                   last ? (uint4*)nullptr
                                                        : (uint4*)(x + xoff));
        }
    }

    // join
    cudaEventRecord(evJ, s2);
    cudaStreamWaitEvent((cudaStream_t)0, evJ, 0);
}